// round 9
// baseline (speedup 1.0000x reference)
#include <cuda_runtime.h>
#include <cuda_bf16.h>

typedef unsigned int u32;

// ---------------- smem layout (bytes) ----------------
// A region: h planes [128][264]bf16 hi@0 lo@67584 ; later d planes [128][136] hi@0 lo@34816
#define SM_A    0
#define H_LO    67584
#define D_LO    34816
// B region (staging): L1 -> msgs hi/lo + W1t hi/lo ; E1 chunk [128][136]x2 ; D2 chunk [256][72]x2
#define SM_B    135168
#define MS_HI   (SM_B)
#define MS_LO   (SM_B + 6144)
#define W1_HI   (SM_B + 12288)
#define W1_LO   (SM_B + 24576)
#define EB_LO   34816            /* relative to SM_B */
#define DB_LO   36864            /* relative to SM_B */
#define SM_C    (SM_B + 73728)
// const region (float offsets from SM_C)
#define CF_B1   0
#define CF_BE1  256
#define CF_WE2  384
#define CF_BE2  1152
#define CF_WD1  1160
#define CF_BD1  1928
#define CF_BD2  2056
#define CF_WO   2312
#define CF_BO   2568
#define CF_ZP   2572             /* 2*128*6 */
#define CF_OP   4108             /* 2*128 */
#define CF_TOT  4364
#define SMEM_BYTES (SM_C + CF_TOT*4)   /* 226,352 <= 232,448 opt-in */

// pitches (bytes): pad K by 8 bf16 -> conflict-free ldmatrix row addressing
#define P_MS  48     /* msgs / W1t: K=16+8 */
#define P_H   528    /* h: K=256+8 */
#define P_D   272    /* d / E1-B chunk: K=128+8 */
#define P_DB  144    /* D2-B chunk: K=64+8 */

// ---------------- pre-split/transposed bf16 weight images ----------------
__device__ __align__(16) unsigned char g_W1t[24576];    // [256n][24k] hi | lo
__device__ __align__(16) unsigned char g_We1t[139264];  // 2 x ([128n][136k] hi | lo)
__device__ __align__(16) unsigned char g_Wd2t[147456];  // 2 x ([256n][72k]  hi | lo)

// ---------------- helpers ----------------
__device__ __forceinline__ u32 smem_u32(const void* p) {
    u32 a;
    asm("{ .reg .u64 t; cvta.to.shared.u64 t, %1; cvt.u32.u64 %0, t; }"
        : "=r"(a) : "l"(p));
    return a;
}
__device__ __forceinline__ void ldmx4(u32& r0, u32& r1, u32& r2, u32& r3, u32 addr) {
    asm volatile("ldmatrix.sync.aligned.m8n8.x4.shared.b16 {%0,%1,%2,%3}, [%4];"
                 : "=r"(r0), "=r"(r1), "=r"(r2), "=r"(r3) : "r"(addr));
}
__device__ __forceinline__ void mma16816(float* c, u32 a0, u32 a1, u32 a2, u32 a3,
                                         u32 b0, u32 b1) {
    asm volatile("mma.sync.aligned.m16n8k16.row.col.f32.bf16.bf16.f32 "
                 "{%0,%1,%2,%3}, {%4,%5,%6,%7}, {%8,%9}, {%0,%1,%2,%3};"
                 : "+f"(c[0]), "+f"(c[1]), "+f"(c[2]), "+f"(c[3])
                 : "r"(a0), "r"(a1), "r"(a2), "r"(a3), "r"(b0), "r"(b1));
}
// tanh(x) = 1 - 2/(e^{2x}+1), rel err ~1e-6
__device__ __forceinline__ float tanh_f(float x) {
    float e; asm("ex2.approx.f32 %0, %1;" : "=f"(e) : "f"(x * 2.885390082f));
    float r; asm("rcp.approx.f32 %0, %1;" : "=f"(r) : "f"(e + 1.0f));
    return fmaf(-2.0f, r, 1.0f);
}
__device__ __forceinline__ u32 pack_split(float x0, float x1, u32& lo) {
    __nv_bfloat16 h0 = __float2bfloat16(x0), h1 = __float2bfloat16(x1);
    __nv_bfloat16 l0 = __float2bfloat16(x0 - __bfloat162float(h0));
    __nv_bfloat16 l1 = __float2bfloat16(x1 - __bfloat162float(h1));
    lo = (u32)__bfloat16_as_ushort(l0) | ((u32)__bfloat16_as_ushort(l1) << 16);
    return (u32)__bfloat16_as_ushort(h0) | ((u32)__bfloat16_as_ushort(h1) << 16);
}
__device__ __forceinline__ void wsplit(unsigned char* hi, unsigned char* lo, float v) {
    __nv_bfloat16 h = __float2bfloat16(v);
    __nv_bfloat16 l = __float2bfloat16(v - __bfloat162float(h));
    *(__nv_bfloat16*)hi = h;
    *(__nv_bfloat16*)lo = l;
}

// ---------------- prep: transpose + split weights into smem-image layout ----
__global__ void prep_weights(const float* __restrict__ W1,
                             const float* __restrict__ We1,
                             const float* __restrict__ Wd2)
{
    int idx = blockIdx.x * 256 + threadIdx.x;
    if (idx < 6144) {                              // W1t: [256n][24k]
        int n = idx / 24, k = idx % 24;
        float v = (k < 16) ? W1[k * 256 + n] : 0.f;
        wsplit(g_W1t + n * P_MS + k * 2, g_W1t + 12288 + n * P_MS + k * 2, v);
        return;
    }
    idx -= 6144;
    if (idx < 34816) {                             // We1t: 2 x [128n][136k]
        int c = idx / 17408, rst = idx % 17408;
        int n = rst / 136, kk = rst % 136;
        float v = (kk < 128) ? We1[(c * 128 + kk) * 128 + n] : 0.f;
        int base = c * 69632 + n * P_D + kk * 2;
        wsplit(g_We1t + base, g_We1t + base + EB_LO, v);
        return;
    }
    idx -= 34816;
    if (idx < 36864) {                             // Wd2t: 2 x [256n][72k]
        int c = idx / 18432, rst = idx % 18432;
        int n = rst / 72, kk = rst % 72;
        float v = (kk < 64) ? Wd2[(c * 64 + kk) * 256 + n] : 0.f;
        int base = c * 73728 + n * P_DB + kk * 2;
        wsplit(g_Wd2t + base, g_Wd2t + base + DB_LO, v);
    }
}

// ---------------- warp GEMM: 32 rows x (NPAIRS*16) cols, KSTEPS k16-steps ----
template<int KSTEPS, int NPAIRS>
__device__ __forceinline__ void wgemm(float* acc, u32 aBase, int aPitch,
                                      u32 bBase, int bPitch)
{
    const int lane = threadIdx.x & 31;
    const u32 aAddr = aBase + (u32)((lane & 15) * aPitch + ((lane >> 4) << 4));
    const int q = lane >> 3;
    const u32 bAddr = bBase + (u32)((((q >> 1) << 3) + (lane & 7)) * bPitch
                                    + ((q & 1) << 4));
#pragma unroll
    for (int ks = 0; ks < KSTEPS; ++ks) {
        u32 a0, a1, a2, a3, a4, a5, a6, a7;
        ldmx4(a0, a1, a2, a3, aAddr + ks * 32);
        ldmx4(a4, a5, a6, a7, aAddr + 16 * aPitch + ks * 32);
#pragma unroll
        for (int np = 0; np < NPAIRS; ++np) {
            u32 b0, b1, b2, b3;
            ldmx4(b0, b1, b2, b3, bAddr + np * 16 * bPitch + ks * 32);
            mma16816(acc + (0 * 2 * NPAIRS + 2 * np + 0) * 4, a0, a1, a2, a3, b0, b1);
            mma16816(acc + (0 * 2 * NPAIRS + 2 * np + 1) * 4, a0, a1, a2, a3, b2, b3);
            mma16816(acc + (1 * 2 * NPAIRS + 2 * np + 0) * 4, a4, a5, a6, a7, b0, b1);
            mma16816(acc + (1 * 2 * NPAIRS + 2 * np + 1) * 4, a4, a5, a6, a7, b2, b3);
        }
    }
}

__device__ __forceinline__ void cpy16(unsigned char* dst, const unsigned char* src,
                                      int n16, int tid)
{
    const uint4* s = (const uint4*)src;
    uint4* d = (uint4*)dst;
    for (int i = tid; i < n16; i += 256) d[i] = s[i];
}

// ---------------- main fused kernel ----------------
__global__ void __launch_bounds__(256, 1)
gnn_mma_kernel(const float* __restrict__ edge_attr,
               const float* __restrict__ b1,  const float* __restrict__ be1,
               const float* __restrict__ We2, const float* __restrict__ be2,
               const float* __restrict__ Wd1, const float* __restrict__ bd1,
               const float* __restrict__ bd2, const float* __restrict__ Wo,
               const float* __restrict__ bo,
               float* __restrict__ out, int Nn, int ntiles)
{
    extern __shared__ unsigned char smem[];
    float* cf = (float*)(smem + SM_C);
    const int tid = threadIdx.x;
    const int w = tid >> 5, lane = tid & 31;
    const int g = lane >> 2, t = lane & 3;
    const int warpM = (w & 3) * 32;
    const int ngrp = w >> 2;
    const int wN256 = ngrp * 128, wN128 = ngrp * 64;
    const u32 sb = smem_u32(smem);

    // constants
    if (tid < 256) cf[CF_B1 + tid] = b1[tid];
    if (tid < 128) cf[CF_BE1 + tid] = be1[tid];
    for (int i = tid; i < 768; i += 256) cf[CF_WE2 + i] = We2[i];
    if (tid < 6)   cf[CF_BE2 + tid] = be2[tid];
    for (int i = tid; i < 768; i += 256) cf[CF_WD1 + i] = Wd1[i];
    if (tid < 128) cf[CF_BD1 + tid] = bd1[tid];
    if (tid < 256) cf[CF_BD2 + tid] = bd2[tid];
    if (tid < 256) cf[CF_WO  + tid] = Wo[tid];
    if (tid == 0)  cf[CF_BO] = bo[0];

    for (int tile = blockIdx.x; tile < ntiles; tile += gridDim.x) {
        const int nb = tile * 128;
        __syncthreads();                      // prev tile fully consumed

        // ---- msgs -> split planes; W1 images -> smem ----
        if (tid < 128) {
            float f[16];
            const int node = nb + tid;
            if (node < Nn) {
                const float4* p = (const float4*)(edge_attr + (size_t)node * 16);
#pragma unroll
                for (int q4 = 0; q4 < 4; ++q4) {
                    float4 v = p[q4];
                    f[4*q4+0]=v.x; f[4*q4+1]=v.y; f[4*q4+2]=v.z; f[4*q4+3]=v.w;
                }
            } else {
#pragma unroll
                for (int i = 0; i < 16; ++i) f[i] = 0.f;
            }
#pragma unroll
            for (int kp = 0; kp < 8; ++kp) {
                u32 lo; u32 hi = pack_split(f[2*kp], f[2*kp+1], lo);
                *(u32*)(smem + MS_HI + tid * P_MS + kp * 4) = hi;
                *(u32*)(smem + MS_LO + tid * P_MS + kp * 4) = lo;
            }
        }
        cpy16(smem + W1_HI, g_W1t, 1536, tid);   // hi+lo contiguous
        __syncthreads();

        // ---- L1: [128x16] @ [16x256] -> h ----
        {
            float acc[128];
#pragma unroll
            for (int i = 0; i < 128; ++i) acc[i] = 0.f;
#pragma unroll
            for (int p = 0; p < 3; ++p)
                wgemm<1, 8>(acc,
                    sb + MS_HI + (p == 1 ? 6144u : 0u) + warpM * P_MS, P_MS,
                    sb + W1_HI + (p == 2 ? 12288u : 0u) + wN256 * P_MS, P_MS);
            // epilogue: bias+tanh+split -> h planes
#pragma unroll
            for (int im = 0; im < 2; ++im)
#pragma unroll
            for (int jn = 0; jn < 16; ++jn) {
                const int idx = (im * 16 + jn) * 4;
                const int c = wN256 + 8 * jn + 2 * t;
                const int r = warpM + 16 * im + g;
                u32 lo;
                u32 hi = pack_split(tanh_f(acc[idx+0] + cf[CF_B1 + c]),
                                    tanh_f(acc[idx+1] + cf[CF_B1 + c + 1]), lo);
                *(u32*)(smem + SM_A + r * P_H + c * 2) = hi;
                *(u32*)(smem + SM_A + H_LO + r * P_H + c * 2) = lo;
                hi = pack_split(tanh_f(acc[idx+2] + cf[CF_B1 + c]),
                                tanh_f(acc[idx+3] + cf[CF_B1 + c + 1]), lo);
                *(u32*)(smem + SM_A + (r + 8) * P_H + c * 2) = hi;
                *(u32*)(smem + SM_A + H_LO + (r + 8) * P_H + c * 2) = lo;
            }
        }
        __syncthreads();

        // ---- E1: [128x256] @ [256x128], K chunked by 128 ----
        {
            float acc[64];
#pragma unroll
            for (int i = 0; i < 64; ++i) acc[i] = 0.f;
            for (int c = 0; c < 2; ++c) {
                cpy16(smem + SM_B, g_We1t + c * 69632, 4352, tid);
                __syncthreads();
#pragma unroll
                for (int p = 0; p < 3; ++p)
                    wgemm<8, 4>(acc,
                        sb + SM_A + (p == 1 ? (u32)H_LO : 0u) + warpM * P_H + c * 256, P_H,
                        sb + SM_B + (p == 2 ? (u32)EB_LO : 0u) + wN128 * P_D, P_D);
                __syncthreads();
            }
            // epilogue: tanh -> z partials (E2)
            float zp[24];
#pragma unroll
            for (int i = 0; i < 24; ++i) zp[i] = 0.f;
#pragma unroll
            for (int im = 0; im < 2; ++im)
#pragma unroll
            for (int jn = 0; jn < 8; ++jn) {
                const int idx = (im * 8 + jn) * 4;
                const int c = wN128 + 8 * jn + 2 * t;
                const float h0 = tanh_f(acc[idx+0] + cf[CF_BE1 + c]);
                const float h1 = tanh_f(acc[idx+1] + cf[CF_BE1 + c + 1]);
                const float h2 = tanh_f(acc[idx+2] + cf[CF_BE1 + c]);
                const float h3 = tanh_f(acc[idx+3] + cf[CF_BE1 + c + 1]);
                const float* w0 = &cf[CF_WE2 + c * 6];
                const float* w1 = &cf[CF_WE2 + (c + 1) * 6];
#pragma unroll
                for (int j = 0; j < 6; ++j) {
                    zp[(im*2+0)*6+j] += h0 * w0[j] + h1 * w1[j];
                    zp[(im*2+1)*6+j] += h2 * w0[j] + h3 * w1[j];
                }
            }
#pragma unroll
            for (int i = 0; i < 24; ++i) {
                zp[i] += __shfl_xor_sync(0xffffffffu, zp[i], 1);
                zp[i] += __shfl_xor_sync(0xffffffffu, zp[i], 2);
            }
            if (t == 0) {
#pragma unroll
                for (int im = 0; im < 2; ++im)
#pragma unroll
                for (int rh = 0; rh < 2; ++rh) {
                    const int r = warpM + 16 * im + 8 * rh + g;
#pragma unroll
                    for (int j = 0; j < 6; ++j)
                        cf[CF_ZP + (ngrp * 128 + r) * 6 + j] = zp[(im*2+rh)*6+j];
                }
            }
        }
        __syncthreads();

        // ---- E2 finish + D1: z -> d planes (scalar, tiny) ----
        {
            const int r = tid >> 1;
            const int ih = (tid & 1) * 64;
            float z[6];
#pragma unroll
            for (int j = 0; j < 6; ++j)
                z[j] = tanh_f(cf[CF_ZP + r * 6 + j] + cf[CF_ZP + 768 + r * 6 + j]
                              + cf[CF_BE2 + j]);
#pragma unroll 8
            for (int i = ih; i < ih + 64; i += 2) {
                float d0 = cf[CF_BD1 + i], d1 = cf[CF_BD1 + i + 1];
#pragma unroll
                for (int j = 0; j < 6; ++j) {
                    d0 = fmaf(z[j], cf[CF_WD1 + j * 128 + i],     d0);
                    d1 = fmaf(z[j], cf[CF_WD1 + j * 128 + i + 1], d1);
                }
                u32 lo; u32 hi = pack_split(tanh_f(d0), tanh_f(d1), lo);
                *(u32*)(smem + SM_A + r * P_D + i * 2) = hi;
                *(u32*)(smem + SM_A + D_LO + r * P_D + i * 2) = lo;
            }
        }
        __syncthreads();

        // ---- D2: [128x128] @ [128x256], K chunked by 64 ----
        {
            float acc[128];
#pragma unroll
            for (int i = 0; i < 128; ++i) acc[i] = 0.f;
            for (int c = 0; c < 2; ++c) {
                cpy16(smem + SM_B, g_Wd2t + c * 73728, 4608, tid);
                __syncthreads();
#pragma unroll
                for (int p = 0; p < 3; ++p)
                    wgemm<4, 8>(acc,
                        sb + SM_A + (p == 1 ? (u32)D_LO : 0u) + warpM * P_D + c * 128, P_D,
                        sb + SM_B + (p == 2 ? (u32)DB_LO : 0u) + wN256 * P_DB, P_DB);
                __syncthreads();
            }
            // epilogue: O-layer row partial sums
            float op[4] = {0.f, 0.f, 0.f, 0.f};
#pragma unroll
            for (int im = 0; im < 2; ++im)
#pragma unroll
            for (int jn = 0; jn < 16; ++jn) {
                const int idx = (im * 16 + jn) * 4;
                const int c = wN256 + 8 * jn + 2 * t;
                op[im*2+0] += tanh_f(acc[idx+0] + cf[CF_BD2 + c])     * cf[CF_WO + c]
                            + tanh_f(acc[idx+1] + cf[CF_BD2 + c + 1]) * cf[CF_WO + c + 1];
                op[im*2+1] += tanh_f(acc[idx+2] + cf[CF_BD2 + c])     * cf[CF_WO + c]
                            + tanh_f(acc[idx+3] + cf[CF_BD2 + c + 1]) * cf[CF_WO + c + 1];
            }
#pragma unroll
            for (int i = 0; i < 4; ++i) {
                op[i] += __shfl_xor_sync(0xffffffffu, op[i], 1);
                op[i] += __shfl_xor_sync(0xffffffffu, op[i], 2);
            }
            if (t == 0) {
#pragma unroll
                for (int im = 0; im < 2; ++im)
#pragma unroll
                for (int rh = 0; rh < 2; ++rh)
                    cf[CF_OP + ngrp * 128 + warpM + 16 * im + 8 * rh + g] = op[im*2+rh];
            }
        }
        __syncthreads();

        if (tid < 128) {
            const float v = cf[CF_OP + tid] + cf[CF_OP + 128 + tid] + cf[CF_BO];
            float e;  asm("ex2.approx.f32 %0, %1;" : "=f"(e)  : "f"(-1.442695041f * v));
            float sg; asm("rcp.approx.f32 %0, %1;" : "=f"(sg) : "f"(1.0f + e));
            if (nb + tid < Nn) out[nb + tid] = sg;
        }
    }
}

// ---------------- launch ----------------
extern "C" void kernel_launch(void* const* d_in, const int* in_sizes, int n_in,
                              void* d_out, int out_size)
{
    // order: x, edge_index, edge_attr, W1, b1, We1, be1, We2, be2,
    //        Wd1, bd1, Wd2, bd2, Wo, bo
    const float* edge_attr = (const float*)d_in[2];
    const float* W1  = (const float*)d_in[3];
    const float* b1  = (const float*)d_in[4];
    const float* We1 = (const float*)d_in[5];
    const float* be1 = (const float*)d_in[6];
    const float* We2 = (const float*)d_in[7];
    const float* be2 = (const float*)d_in[8];
    const float* Wd1 = (const float*)d_in[9];
    const float* bd1 = (const float*)d_in[10];
    const float* Wd2 = (const float*)d_in[11];
    const float* bd2 = (const float*)d_in[12];
    const float* Wo  = (const float*)d_in[13];
    const float* bo  = (const float*)d_in[14];
    float* out = (float*)d_out;

    const int Nn = out_size;
    const int ntiles = (Nn + 127) / 128;

    prep_weights<<<304, 256>>>(W1, We1, Wd2);   // 77824 elements

    cudaFuncSetAttribute(gnn_mma_kernel,
                         cudaFuncAttributeMaxDynamicSharedMemorySize, SMEM_BYTES);
    int sms = 148;
    cudaDeviceGetAttribute(&sms, cudaDevAttrMultiProcessorCount, 0);
    const int grid = ntiles < sms ? ntiles : sms;

    gnn_mma_kernel<<<grid, 256, SMEM_BYTES>>>(
        edge_attr, b1, be1, We2, be2, Wd1, bd1, bd2, Wo, bo, out, Nn, ntiles);
}

// round 10
// speedup vs baseline: 1.0033x; 1.0033x over previous
#include <cuda_runtime.h>
#include <cuda_bf16.h>

typedef unsigned int u32;

// ---------------- smem layout (bytes) ----------------
// A region: h planes [128][264]bf16 hi@0 lo@67584 ; later d planes [128][136] hi@0 lo@34816
#define SM_A    0
#define H_LO    67584
#define D_LO    34816
// B region (staging): L1 -> msgs hi/lo + W1t hi/lo ; E1 chunk [128][136]x2 ; D2 chunk [256][72]x2
#define SM_B    135168
#define MS_HI   (SM_B)
#define MS_LO   (SM_B + 6144)
#define W1_HI   (SM_B + 12288)
#define W1_LO   (SM_B + 24576)
#define EB_LO   34816            /* relative to SM_B */
#define DB_LO   36864            /* relative to SM_B */
#define SM_C    (SM_B + 73728)
// const region (float offsets from SM_C)
#define CF_B1   0
#define CF_BE1  256
#define CF_WE2  384
#define CF_BE2  1152
#define CF_WD1  1160
#define CF_BD1  1928
#define CF_BD2  2056
#define CF_WO   2312
#define CF_BO   2568
#define CF_ZP   2572             /* 2*128*6 */
#define CF_OP   4108             /* 2*128 */
#define CF_TOT  4364
#define SMEM_BYTES (SM_C + CF_TOT*4)   /* 226,352 <= 232,448 opt-in */

// pitches (bytes): pad K by 8 bf16 -> conflict-free ldmatrix row addressing
#define P_MS  48     /* msgs / W1t: K=16+8 */
#define P_H   528    /* h: K=256+8 */
#define P_D   272    /* d / E1-B chunk: K=128+8 */
#define P_DB  144    /* D2-B chunk: K=64+8 */

// ---------------- pre-split/transposed bf16 weight images ----------------
__device__ __align__(16) unsigned char g_W1t[24576];    // [256n][24k] hi | lo
__device__ __align__(16) unsigned char g_We1t[139264];  // 2 x ([128n][136k] hi | lo)
__device__ __align__(16) unsigned char g_Wd2t[147456];  // 2 x ([256n][72k]  hi | lo)

// ---------------- helpers ----------------
__device__ __forceinline__ u32 smem_u32(const void* p) {
    u32 a;
    asm("{ .reg .u64 t; cvta.to.shared.u64 t, %1; cvt.u32.u64 %0, t; }"
        : "=r"(a) : "l"(p));
    return a;
}
__device__ __forceinline__ void ldmx4(u32& r0, u32& r1, u32& r2, u32& r3, u32 addr) {
    asm volatile("ldmatrix.sync.aligned.m8n8.x4.shared.b16 {%0,%1,%2,%3}, [%4];"
                 : "=r"(r0), "=r"(r1), "=r"(r2), "=r"(r3) : "r"(addr));
}
__device__ __forceinline__ void mma16816(float* c, u32 a0, u32 a1, u32 a2, u32 a3,
                                         u32 b0, u32 b1) {
    asm volatile("mma.sync.aligned.m16n8k16.row.col.f32.bf16.bf16.f32 "
                 "{%0,%1,%2,%3}, {%4,%5,%6,%7}, {%8,%9}, {%0,%1,%2,%3};"
                 : "+f"(c[0]), "+f"(c[1]), "+f"(c[2]), "+f"(c[3])
                 : "r"(a0), "r"(a1), "r"(a2), "r"(a3), "r"(b0), "r"(b1));
}
// tanh(x) = 1 - 2/(e^{2x}+1), rel err ~1e-6
__device__ __forceinline__ float tanh_f(float x) {
    float e; asm("ex2.approx.f32 %0, %1;" : "=f"(e) : "f"(x * 2.885390082f));
    float r; asm("rcp.approx.f32 %0, %1;" : "=f"(r) : "f"(e + 1.0f));
    return fmaf(-2.0f, r, 1.0f);
}
__device__ __forceinline__ u32 pack_split(float x0, float x1, u32& lo) {
    __nv_bfloat16 h0 = __float2bfloat16(x0), h1 = __float2bfloat16(x1);
    __nv_bfloat16 l0 = __float2bfloat16(x0 - __bfloat162float(h0));
    __nv_bfloat16 l1 = __float2bfloat16(x1 - __bfloat162float(h1));
    lo = (u32)__bfloat16_as_ushort(l0) | ((u32)__bfloat16_as_ushort(l1) << 16);
    return (u32)__bfloat16_as_ushort(h0) | ((u32)__bfloat16_as_ushort(h1) << 16);
}
__device__ __forceinline__ void wsplit(unsigned char* hi, unsigned char* lo, float v) {
    __nv_bfloat16 h = __float2bfloat16(v);
    __nv_bfloat16 l = __float2bfloat16(v - __bfloat162float(h));
    *(__nv_bfloat16*)hi = h;
    *(__nv_bfloat16*)lo = l;
}

// ---------------- prep: transpose + split weights into smem-image layout ----
__global__ void prep_weights(const float* __restrict__ W1,
                             const float* __restrict__ We1,
                             const float* __restrict__ Wd2)
{
    int idx = blockIdx.x * 256 + threadIdx.x;
    if (idx < 6144) {                              // W1t: [256n][24k]
        int n = idx / 24, k = idx % 24;
        float v = (k < 16) ? W1[k * 256 + n] : 0.f;
        wsplit(g_W1t + n * P_MS + k * 2, g_W1t + 12288 + n * P_MS + k * 2, v);
        return;
    }
    idx -= 6144;
    if (idx < 34816) {                             // We1t: 2 x [128n][136k]
        int c = idx / 17408, rst = idx % 17408;
        int n = rst / 136, kk = rst % 136;
        float v = (kk < 128) ? We1[(c * 128 + kk) * 128 + n] : 0.f;
        int base = c * 69632 + n * P_D + kk * 2;
        wsplit(g_We1t + base, g_We1t + base + EB_LO, v);
        return;
    }
    idx -= 34816;
    if (idx < 36864) {                             // Wd2t: 2 x [256n][72k]
        int c = idx / 18432, rst = idx % 18432;
        int n = rst / 72, kk = rst % 72;
        float v = (kk < 64) ? Wd2[(c * 64 + kk) * 256 + n] : 0.f;
        int base = c * 73728 + n * P_DB + kk * 2;
        wsplit(g_Wd2t + base, g_Wd2t + base + DB_LO, v);
    }
}

// ---------------- warp GEMM: 32 rows x (NPAIRS*16) cols, KSTEPS k16-steps ----
template<int KSTEPS, int NPAIRS>
__device__ __forceinline__ void wgemm(float* acc, u32 aBase, int aPitch,
                                      u32 bBase, int bPitch)
{
    const int lane = threadIdx.x & 31;
    const u32 aAddr = aBase + (u32)((lane & 15) * aPitch + ((lane >> 4) << 4));
    const int q = lane >> 3;
    const u32 bAddr = bBase + (u32)((((q >> 1) << 3) + (lane & 7)) * bPitch
                                    + ((q & 1) << 4));
#pragma unroll
    for (int ks = 0; ks < KSTEPS; ++ks) {
        u32 a0, a1, a2, a3, a4, a5, a6, a7;
        ldmx4(a0, a1, a2, a3, aAddr + ks * 32);
        ldmx4(a4, a5, a6, a7, aAddr + 16 * aPitch + ks * 32);
#pragma unroll
        for (int np = 0; np < NPAIRS; ++np) {
            u32 b0, b1, b2, b3;
            ldmx4(b0, b1, b2, b3, bAddr + np * 16 * bPitch + ks * 32);
            mma16816(acc + (0 * 2 * NPAIRS + 2 * np + 0) * 4, a0, a1, a2, a3, b0, b1);
            mma16816(acc + (0 * 2 * NPAIRS + 2 * np + 1) * 4, a0, a1, a2, a3, b2, b3);
            mma16816(acc + (1 * 2 * NPAIRS + 2 * np + 0) * 4, a4, a5, a6, a7, b0, b1);
            mma16816(acc + (1 * 2 * NPAIRS + 2 * np + 1) * 4, a4, a5, a6, a7, b2, b3);
        }
    }
}

__device__ __forceinline__ void cpy16(unsigned char* dst, const unsigned char* src,
                                      int n16, int tid)
{
    const uint4* s = (const uint4*)src;
    uint4* d = (uint4*)dst;
    for (int i = tid; i < n16; i += 256) d[i] = s[i];
}

// ---------------- main fused kernel ----------------
__global__ void __launch_bounds__(256, 1)
gnn_mma_kernel(const float* __restrict__ edge_attr,
               const float* __restrict__ b1,  const float* __restrict__ be1,
               const float* __restrict__ We2, const float* __restrict__ be2,
               const float* __restrict__ Wd1, const float* __restrict__ bd1,
               const float* __restrict__ bd2, const float* __restrict__ Wo,
               const float* __restrict__ bo,
               float* __restrict__ out, int Nn, int ntiles)
{
    extern __shared__ unsigned char smem[];
    float* cf = (float*)(smem + SM_C);
    const int tid = threadIdx.x;
    const int w = tid >> 5, lane = tid & 31;
    const int g = lane >> 2, t = lane & 3;
    const int warpM = (w & 3) * 32;
    const int ngrp = w >> 2;
    const int wN256 = ngrp * 128, wN128 = ngrp * 64;
    const u32 sb = smem_u32(smem);

    // constants
    if (tid < 256) cf[CF_B1 + tid] = b1[tid];
    if (tid < 128) cf[CF_BE1 + tid] = be1[tid];
    for (int i = tid; i < 768; i += 256) cf[CF_WE2 + i] = We2[i];
    if (tid < 6)   cf[CF_BE2 + tid] = be2[tid];
    for (int i = tid; i < 768; i += 256) cf[CF_WD1 + i] = Wd1[i];
    if (tid < 128) cf[CF_BD1 + tid] = bd1[tid];
    if (tid < 256) cf[CF_BD2 + tid] = bd2[tid];
    if (tid < 256) cf[CF_WO  + tid] = Wo[tid];
    if (tid == 0)  cf[CF_BO] = bo[0];

    for (int tile = blockIdx.x; tile < ntiles; tile += gridDim.x) {
        const int nb = tile * 128;
        __syncthreads();                      // prev tile fully consumed

        // ---- msgs -> split planes; W1 images -> smem ----
        if (tid < 128) {
            float f[16];
            const int node = nb + tid;
            if (node < Nn) {
                const float4* p = (const float4*)(edge_attr + (size_t)node * 16);
#pragma unroll
                for (int q4 = 0; q4 < 4; ++q4) {
                    float4 v = p[q4];
                    f[4*q4+0]=v.x; f[4*q4+1]=v.y; f[4*q4+2]=v.z; f[4*q4+3]=v.w;
                }
            } else {
#pragma unroll
                for (int i = 0; i < 16; ++i) f[i] = 0.f;
            }
#pragma unroll
            for (int kp = 0; kp < 8; ++kp) {
                u32 lo; u32 hi = pack_split(f[2*kp], f[2*kp+1], lo);
                *(u32*)(smem + MS_HI + tid * P_MS + kp * 4) = hi;
                *(u32*)(smem + MS_LO + tid * P_MS + kp * 4) = lo;
            }
        }
        cpy16(smem + W1_HI, g_W1t, 1536, tid);   // hi+lo contiguous
        __syncthreads();

        // ---- L1: [128x16] @ [16x256] -> h ----
        {
            float acc[128];
#pragma unroll
            for (int i = 0; i < 128; ++i) acc[i] = 0.f;
#pragma unroll
            for (int p = 0; p < 3; ++p)
                wgemm<1, 8>(acc,
                    sb + MS_HI + (p == 1 ? 6144u : 0u) + warpM * P_MS, P_MS,
                    sb + W1_HI + (p == 2 ? 12288u : 0u) + wN256 * P_MS, P_MS);
            // epilogue: bias+tanh+split -> h planes
#pragma unroll
            for (int im = 0; im < 2; ++im)
#pragma unroll
            for (int jn = 0; jn < 16; ++jn) {
                const int idx = (im * 16 + jn) * 4;
                const int c = wN256 + 8 * jn + 2 * t;
                const int r = warpM + 16 * im + g;
                u32 lo;
                u32 hi = pack_split(tanh_f(acc[idx+0] + cf[CF_B1 + c]),
                                    tanh_f(acc[idx+1] + cf[CF_B1 + c + 1]), lo);
                *(u32*)(smem + SM_A + r * P_H + c * 2) = hi;
                *(u32*)(smem + SM_A + H_LO + r * P_H + c * 2) = lo;
                hi = pack_split(tanh_f(acc[idx+2] + cf[CF_B1 + c]),
                                tanh_f(acc[idx+3] + cf[CF_B1 + c + 1]), lo);
                *(u32*)(smem + SM_A + (r + 8) * P_H + c * 2) = hi;
                *(u32*)(smem + SM_A + H_LO + (r + 8) * P_H + c * 2) = lo;
            }
        }
        __syncthreads();

        // ---- E1: [128x256] @ [256x128], K chunked by 128 ----
        {
            float acc[64];
#pragma unroll
            for (int i = 0; i < 64; ++i) acc[i] = 0.f;
            for (int c = 0; c < 2; ++c) {
                cpy16(smem + SM_B, g_We1t + c * 69632, 4352, tid);
                __syncthreads();
#pragma unroll
                for (int p = 0; p < 3; ++p)
                    wgemm<8, 4>(acc,
                        sb + SM_A + (p == 1 ? (u32)H_LO : 0u) + warpM * P_H + c * 256, P_H,
                        sb + SM_B + (p == 2 ? (u32)EB_LO : 0u) + wN128 * P_D, P_D);
                __syncthreads();
            }
            // epilogue: tanh -> z partials (E2)
            float zp[24];
#pragma unroll
            for (int i = 0; i < 24; ++i) zp[i] = 0.f;
#pragma unroll
            for (int im = 0; im < 2; ++im)
#pragma unroll
            for (int jn = 0; jn < 8; ++jn) {
                const int idx = (im * 8 + jn) * 4;
                const int c = wN128 + 8 * jn + 2 * t;
                const float h0 = tanh_f(acc[idx+0] + cf[CF_BE1 + c]);
                const float h1 = tanh_f(acc[idx+1] + cf[CF_BE1 + c + 1]);
                const float h2 = tanh_f(acc[idx+2] + cf[CF_BE1 + c]);
                const float h3 = tanh_f(acc[idx+3] + cf[CF_BE1 + c + 1]);
                const float* w0 = &cf[CF_WE2 + c * 6];
                const float* w1 = &cf[CF_WE2 + (c + 1) * 6];
#pragma unroll
                for (int j = 0; j < 6; ++j) {
                    zp[(im*2+0)*6+j] += h0 * w0[j] + h1 * w1[j];
                    zp[(im*2+1)*6+j] += h2 * w0[j] + h3 * w1[j];
                }
            }
#pragma unroll
            for (int i = 0; i < 24; ++i) {
                zp[i] += __shfl_xor_sync(0xffffffffu, zp[i], 1);
                zp[i] += __shfl_xor_sync(0xffffffffu, zp[i], 2);
            }
            if (t == 0) {
#pragma unroll
                for (int im = 0; im < 2; ++im)
#pragma unroll
                for (int rh = 0; rh < 2; ++rh) {
                    const int r = warpM + 16 * im + 8 * rh + g;
#pragma unroll
                    for (int j = 0; j < 6; ++j)
                        cf[CF_ZP + (ngrp * 128 + r) * 6 + j] = zp[(im*2+rh)*6+j];
                }
            }
        }
        __syncthreads();

        // ---- E2 finish + D1: z -> d planes (scalar, tiny) ----
        {
            const int r = tid >> 1;
            const int ih = (tid & 1) * 64;
            float z[6];
#pragma unroll
            for (int j = 0; j < 6; ++j)
                z[j] = tanh_f(cf[CF_ZP + r * 6 + j] + cf[CF_ZP + 768 + r * 6 + j]
                              + cf[CF_BE2 + j]);
#pragma unroll 8
            for (int i = ih; i < ih + 64; i += 2) {
                float d0 = cf[CF_BD1 + i], d1 = cf[CF_BD1 + i + 1];
#pragma unroll
                for (int j = 0; j < 6; ++j) {
                    d0 = fmaf(z[j], cf[CF_WD1 + j * 128 + i],     d0);
                    d1 = fmaf(z[j], cf[CF_WD1 + j * 128 + i + 1], d1);
                }
                u32 lo; u32 hi = pack_split(tanh_f(d0), tanh_f(d1), lo);
                *(u32*)(smem + SM_A + r * P_D + i * 2) = hi;
                *(u32*)(smem + SM_A + D_LO + r * P_D + i * 2) = lo;
            }
        }
        __syncthreads();

        // ---- D2: [128x128] @ [128x256], K chunked by 64 ----
        {
            float acc[128];
#pragma unroll
            for (int i = 0; i < 128; ++i) acc[i] = 0.f;
            for (int c = 0; c < 2; ++c) {
                cpy16(smem + SM_B, g_Wd2t + c * 73728, 4608, tid);
                __syncthreads();
#pragma unroll
                for (int p = 0; p < 3; ++p)
                    wgemm<4, 8>(acc,
                        sb + SM_A + (p == 1 ? (u32)D_LO : 0u) + warpM * P_D + c * 128, P_D,
                        sb + SM_B + (p == 2 ? (u32)DB_LO : 0u) + wN256 * P_DB, P_DB);
                __syncthreads();
            }
            // epilogue: O-layer row partial sums
            float op[4] = {0.f, 0.f, 0.f, 0.f};
#pragma unroll
            for (int im = 0; im < 2; ++im)
#pragma unroll
            for (int jn = 0; jn < 16; ++jn) {
                const int idx = (im * 16 + jn) * 4;
                const int c = wN256 + 8 * jn + 2 * t;
                op[im*2+0] += tanh_f(acc[idx+0] + cf[CF_BD2 + c])     * cf[CF_WO + c]
                            + tanh_f(acc[idx+1] + cf[CF_BD2 + c + 1]) * cf[CF_WO + c + 1];
                op[im*2+1] += tanh_f(acc[idx+2] + cf[CF_BD2 + c])     * cf[CF_WO + c]
                            + tanh_f(acc[idx+3] + cf[CF_BD2 + c + 1]) * cf[CF_WO + c + 1];
            }
#pragma unroll
            for (int i = 0; i < 4; ++i) {
                op[i] += __shfl_xor_sync(0xffffffffu, op[i], 1);
                op[i] += __shfl_xor_sync(0xffffffffu, op[i], 2);
            }
            if (t == 0) {
#pragma unroll
                for (int im = 0; im < 2; ++im)
#pragma unroll
                for (int rh = 0; rh < 2; ++rh)
                    cf[CF_OP + ngrp * 128 + warpM + 16 * im + 8 * rh + g] = op[im*2+rh];
            }
        }
        __syncthreads();

        if (tid < 128) {
            const float v = cf[CF_OP + tid] + cf[CF_OP + 128 + tid] + cf[CF_BO];
            float e;  asm("ex2.approx.f32 %0, %1;" : "=f"(e)  : "f"(-1.442695041f * v));
            float sg; asm("rcp.approx.f32 %0, %1;" : "=f"(sg) : "f"(1.0f + e));
            if (nb + tid < Nn) out[nb + tid] = sg;
        }
    }
}

// ---------------- launch ----------------
extern "C" void kernel_launch(void* const* d_in, const int* in_sizes, int n_in,
                              void* d_out, int out_size)
{
    // order: x, edge_index, edge_attr, W1, b1, We1, be1, We2, be2,
    //        Wd1, bd1, Wd2, bd2, Wo, bo
    const float* edge_attr = (const float*)d_in[2];
    const float* W1  = (const float*)d_in[3];
    const float* b1  = (const float*)d_in[4];
    const float* We1 = (const float*)d_in[5];
    const float* be1 = (const float*)d_in[6];
    const float* We2 = (const float*)d_in[7];
    const float* be2 = (const float*)d_in[8];
    const float* Wd1 = (const float*)d_in[9];
    const float* bd1 = (const float*)d_in[10];
    const float* Wd2 = (const float*)d_in[11];
    const float* bd2 = (const float*)d_in[12];
    const float* Wo  = (const float*)d_in[13];
    const float* bo  = (const float*)d_in[14];
    float* out = (float*)d_out;

    const int Nn = out_size;
    const int ntiles = (Nn + 127) / 128;

    prep_weights<<<304, 256>>>(W1, We1, Wd2);   // 77824 elements

    cudaFuncSetAttribute(gnn_mma_kernel,
                         cudaFuncAttributeMaxDynamicSharedMemorySize, SMEM_BYTES);
    int sms = 148;
    cudaDeviceGetAttribute(&sms, cudaDevAttrMultiProcessorCount, 0);
    const int grid = ntiles < sms ? ntiles : sms;

    gnn_mma_kernel<<<grid, 256, SMEM_BYTES>>>(
        edge_attr, b1, be1, We2, be2, Wd1, bd1, bd2, Wo, bo, out, Nn, ntiles);
}

// round 11
// speedup vs baseline: 1.0053x; 1.0020x over previous
#include <cuda_runtime.h>
#include <cuda_bf16.h>

typedef unsigned int u32;

// ---------------- smem layout (bytes) ----------------
// A region: h planes [128][264]bf16 hi@0 lo@67584 ; later d planes [128][136] hi@0 lo@34816
#define SM_A    0
#define H_LO    67584
#define D_LO    34816
// B region (staging): L1 -> msgs hi/lo + W1t hi/lo ; E1 chunk [128][136]x2 ; D2 chunk [256][72]x2
#define SM_B    135168
#define MS_HI   (SM_B)
#define MS_LO   (SM_B + 6144)
#define W1_HI   (SM_B + 12288)
#define W1_LO   (SM_B + 24576)
#define EB_LO   34816            /* relative to SM_B */
#define DB_LO   36864            /* relative to SM_B */
#define SM_C    (SM_B + 73728)
// const region (float offsets from SM_C)
#define CF_B1   0
#define CF_BE1  256
#define CF_WE2  384
#define CF_BE2  1152
#define CF_WD1  1160
#define CF_BD1  1928
#define CF_BD2  2056
#define CF_WO   2312
#define CF_BO   2568
#define CF_ZP   2572             /* 2*128*6 */
#define CF_OP   4108             /* 2*128 */
#define CF_TOT  4364
#define SMEM_BYTES (SM_C + CF_TOT*4)   /* 226,352 <= 232,448 opt-in */

// pitches (bytes): pad K by 8 bf16 -> conflict-free ldmatrix row addressing
#define P_MS  48     /* msgs / W1t: K=16+8 */
#define P_H   528    /* h: K=256+8 */
#define P_D   272    /* d / E1-B chunk: K=128+8 */
#define P_DB  144    /* D2-B chunk: K=64+8 */

// ---------------- pre-split/transposed bf16 weight images ----------------
__device__ __align__(16) unsigned char g_W1t[24576];    // [256n][24k] hi | lo
__device__ __align__(16) unsigned char g_We1t[139264];  // 2 x ([128n][136k] hi | lo)
__device__ __align__(16) unsigned char g_Wd2t[147456];  // 2 x ([256n][72k]  hi | lo)

// ---------------- helpers ----------------
__device__ __forceinline__ u32 smem_u32(const void* p) {
    u32 a;
    asm("{ .reg .u64 t; cvta.to.shared.u64 t, %1; cvt.u32.u64 %0, t; }"
        : "=r"(a) : "l"(p));
    return a;
}
__device__ __forceinline__ void ldmx4(u32& r0, u32& r1, u32& r2, u32& r3, u32 addr) {
    asm volatile("ldmatrix.sync.aligned.m8n8.x4.shared.b16 {%0,%1,%2,%3}, [%4];"
                 : "=r"(r0), "=r"(r1), "=r"(r2), "=r"(r3) : "r"(addr));
}
__device__ __forceinline__ void mma16816(float* c, u32 a0, u32 a1, u32 a2, u32 a3,
                                         u32 b0, u32 b1) {
    asm volatile("mma.sync.aligned.m16n8k16.row.col.f32.bf16.bf16.f32 "
                 "{%0,%1,%2,%3}, {%4,%5,%6,%7}, {%8,%9}, {%0,%1,%2,%3};"
                 : "+f"(c[0]), "+f"(c[1]), "+f"(c[2]), "+f"(c[3])
                 : "r"(a0), "r"(a1), "r"(a2), "r"(a3), "r"(b0), "r"(b1));
}
// tanh(x) = 1 - 2/(e^{2x}+1), rel err ~1e-6
__device__ __forceinline__ float tanh_f(float x) {
    float e; asm("ex2.approx.f32 %0, %1;" : "=f"(e) : "f"(x * 2.885390082f));
    float r; asm("rcp.approx.f32 %0, %1;" : "=f"(r) : "f"(e + 1.0f));
    return fmaf(-2.0f, r, 1.0f);
}
__device__ __forceinline__ u32 pack_split(float x0, float x1, u32& lo) {
    __nv_bfloat16 h0 = __float2bfloat16(x0), h1 = __float2bfloat16(x1);
    __nv_bfloat16 l0 = __float2bfloat16(x0 - __bfloat162float(h0));
    __nv_bfloat16 l1 = __float2bfloat16(x1 - __bfloat162float(h1));
    lo = (u32)__bfloat16_as_ushort(l0) | ((u32)__bfloat16_as_ushort(l1) << 16);
    return (u32)__bfloat16_as_ushort(h0) | ((u32)__bfloat16_as_ushort(h1) << 16);
}
__device__ __forceinline__ void wsplit(unsigned char* hi, unsigned char* lo, float v) {
    __nv_bfloat16 h = __float2bfloat16(v);
    __nv_bfloat16 l = __float2bfloat16(v - __bfloat162float(h));
    *(__nv_bfloat16*)hi = h;
    *(__nv_bfloat16*)lo = l;
}

// ---------------- prep: transpose + split weights into smem-image layout ----
__global__ void prep_weights(const float* __restrict__ W1,
                             const float* __restrict__ We1,
                             const float* __restrict__ Wd2)
{
    int idx = blockIdx.x * 256 + threadIdx.x;
    if (idx < 6144) {                              // W1t: [256n][24k]
        int n = idx / 24, k = idx % 24;
        float v = (k < 16) ? W1[k * 256 + n] : 0.f;
        wsplit(g_W1t + n * P_MS + k * 2, g_W1t + 12288 + n * P_MS + k * 2, v);
        return;
    }
    idx -= 6144;
    if (idx < 34816) {                             // We1t: 2 x [128n][136k]
        int c = idx / 17408, rst = idx % 17408;
        int n = rst / 136, kk = rst % 136;
        float v = (kk < 128) ? We1[(c * 128 + kk) * 128 + n] : 0.f;
        int base = c * 69632 + n * P_D + kk * 2;
        wsplit(g_We1t + base, g_We1t + base + EB_LO, v);
        return;
    }
    idx -= 34816;
    if (idx < 36864) {                             // Wd2t: 2 x [256n][72k]
        int c = idx / 18432, rst = idx % 18432;
        int n = rst / 72, kk = rst % 72;
        float v = (kk < 64) ? Wd2[(c * 64 + kk) * 256 + n] : 0.f;
        int base = c * 73728 + n * P_DB + kk * 2;
        wsplit(g_Wd2t + base, g_Wd2t + base + DB_LO, v);
    }
}

// ---------------- warp GEMM: 32 rows x (NPAIRS*16) cols, KSTEPS k16-steps ----
template<int KSTEPS, int NPAIRS>
__device__ __forceinline__ void wgemm(float* acc, u32 aBase, int aPitch,
                                      u32 bBase, int bPitch)
{
    const int lane = threadIdx.x & 31;
    const u32 aAddr = aBase + (u32)((lane & 15) * aPitch + ((lane >> 4) << 4));
    const int q = lane >> 3;
    const u32 bAddr = bBase + (u32)((((q >> 1) << 3) + (lane & 7)) * bPitch
                                    + ((q & 1) << 4));
#pragma unroll
    for (int ks = 0; ks < KSTEPS; ++ks) {
        u32 a0, a1, a2, a3, a4, a5, a6, a7;
        ldmx4(a0, a1, a2, a3, aAddr + ks * 32);
        ldmx4(a4, a5, a6, a7, aAddr + 16 * aPitch + ks * 32);
#pragma unroll
        for (int np = 0; np < NPAIRS; ++np) {
            u32 b0, b1, b2, b3;
            ldmx4(b0, b1, b2, b3, bAddr + np * 16 * bPitch + ks * 32);
            mma16816(acc + (0 * 2 * NPAIRS + 2 * np + 0) * 4, a0, a1, a2, a3, b0, b1);
            mma16816(acc + (0 * 2 * NPAIRS + 2 * np + 1) * 4, a0, a1, a2, a3, b2, b3);
            mma16816(acc + (1 * 2 * NPAIRS + 2 * np + 0) * 4, a4, a5, a6, a7, b0, b1);
            mma16816(acc + (1 * 2 * NPAIRS + 2 * np + 1) * 4, a4, a5, a6, a7, b2, b3);
        }
    }
}

__device__ __forceinline__ void cpy16(unsigned char* dst, const unsigned char* src,
                                      int n16, int tid)
{
    const uint4* s = (const uint4*)src;
    uint4* d = (uint4*)dst;
    for (int i = tid; i < n16; i += 256) d[i] = s[i];
}

// ---------------- main fused kernel ----------------
__global__ void __launch_bounds__(256, 1)
gnn_mma_kernel(const float* __restrict__ edge_attr,
               const float* __restrict__ b1,  const float* __restrict__ be1,
               const float* __restrict__ We2, const float* __restrict__ be2,
               const float* __restrict__ Wd1, const float* __restrict__ bd1,
               const float* __restrict__ bd2, const float* __restrict__ Wo,
               const float* __restrict__ bo,
               float* __restrict__ out, int Nn, int ntiles)
{
    extern __shared__ unsigned char smem[];
    float* cf = (float*)(smem + SM_C);
    const int tid = threadIdx.x;
    const int w = tid >> 5, lane = tid & 31;
    const int g = lane >> 2, t = lane & 3;
    const int warpM = (w & 3) * 32;
    const int ngrp = w >> 2;
    const int wN256 = ngrp * 128, wN128 = ngrp * 64;
    const u32 sb = smem_u32(smem);

    // constants
    if (tid < 256) cf[CF_B1 + tid] = b1[tid];
    if (tid < 128) cf[CF_BE1 + tid] = be1[tid];
    for (int i = tid; i < 768; i += 256) cf[CF_WE2 + i] = We2[i];
    if (tid < 6)   cf[CF_BE2 + tid] = be2[tid];
    for (int i = tid; i < 768; i += 256) cf[CF_WD1 + i] = Wd1[i];
    if (tid < 128) cf[CF_BD1 + tid] = bd1[tid];
    if (tid < 256) cf[CF_BD2 + tid] = bd2[tid];
    if (tid < 256) cf[CF_WO  + tid] = Wo[tid];
    if (tid == 0)  cf[CF_BO] = bo[0];

    for (int tile = blockIdx.x; tile < ntiles; tile += gridDim.x) {
        const int nb = tile * 128;
        __syncthreads();                      // prev tile fully consumed

        // ---- msgs -> split planes; W1 images -> smem ----
        if (tid < 128) {
            float f[16];
            const int node = nb + tid;
            if (node < Nn) {
                const float4* p = (const float4*)(edge_attr + (size_t)node * 16);
#pragma unroll
                for (int q4 = 0; q4 < 4; ++q4) {
                    float4 v = p[q4];
                    f[4*q4+0]=v.x; f[4*q4+1]=v.y; f[4*q4+2]=v.z; f[4*q4+3]=v.w;
                }
            } else {
#pragma unroll
                for (int i = 0; i < 16; ++i) f[i] = 0.f;
            }
#pragma unroll
            for (int kp = 0; kp < 8; ++kp) {
                u32 lo; u32 hi = pack_split(f[2*kp], f[2*kp+1], lo);
                *(u32*)(smem + MS_HI + tid * P_MS + kp * 4) = hi;
                *(u32*)(smem + MS_LO + tid * P_MS + kp * 4) = lo;
            }
        }
        cpy16(smem + W1_HI, g_W1t, 1536, tid);   // hi+lo contiguous
        __syncthreads();

        // ---- L1: [128x16] @ [16x256] -> h ----
        {
            float acc[128];
#pragma unroll
            for (int i = 0; i < 128; ++i) acc[i] = 0.f;
#pragma unroll
            for (int p = 0; p < 3; ++p)
                wgemm<1, 8>(acc,
                    sb + MS_HI + (p == 1 ? 6144u : 0u) + warpM * P_MS, P_MS,
                    sb + W1_HI + (p == 2 ? 12288u : 0u) + wN256 * P_MS, P_MS);
            // epilogue: bias+tanh+split -> h planes
#pragma unroll
            for (int im = 0; im < 2; ++im)
#pragma unroll
            for (int jn = 0; jn < 16; ++jn) {
                const int idx = (im * 16 + jn) * 4;
                const int c = wN256 + 8 * jn + 2 * t;
                const int r = warpM + 16 * im + g;
                u32 lo;
                u32 hi = pack_split(tanh_f(acc[idx+0] + cf[CF_B1 + c]),
                                    tanh_f(acc[idx+1] + cf[CF_B1 + c + 1]), lo);
                *(u32*)(smem + SM_A + r * P_H + c * 2) = hi;
                *(u32*)(smem + SM_A + H_LO + r * P_H + c * 2) = lo;
                hi = pack_split(tanh_f(acc[idx+2] + cf[CF_B1 + c]),
                                tanh_f(acc[idx+3] + cf[CF_B1 + c + 1]), lo);
                *(u32*)(smem + SM_A + (r + 8) * P_H + c * 2) = hi;
                *(u32*)(smem + SM_A + H_LO + (r + 8) * P_H + c * 2) = lo;
            }
        }
        __syncthreads();

        // ---- E1: [128x256] @ [256x128], K chunked by 128 ----
        {
            float acc[64];
#pragma unroll
            for (int i = 0; i < 64; ++i) acc[i] = 0.f;
            for (int c = 0; c < 2; ++c) {
                cpy16(smem + SM_B, g_We1t + c * 69632, 4352, tid);
                __syncthreads();
#pragma unroll
                for (int p = 0; p < 3; ++p)
                    wgemm<8, 4>(acc,
                        sb + SM_A + (p == 1 ? (u32)H_LO : 0u) + warpM * P_H + c * 256, P_H,
                        sb + SM_B + (p == 2 ? (u32)EB_LO : 0u) + wN128 * P_D, P_D);
                __syncthreads();
            }
            // epilogue: tanh -> z partials (E2)
            float zp[24];
#pragma unroll
            for (int i = 0; i < 24; ++i) zp[i] = 0.f;
#pragma unroll
            for (int im = 0; im < 2; ++im)
#pragma unroll
            for (int jn = 0; jn < 8; ++jn) {
                const int idx = (im * 8 + jn) * 4;
                const int c = wN128 + 8 * jn + 2 * t;
                const float h0 = tanh_f(acc[idx+0] + cf[CF_BE1 + c]);
                const float h1 = tanh_f(acc[idx+1] + cf[CF_BE1 + c + 1]);
                const float h2 = tanh_f(acc[idx+2] + cf[CF_BE1 + c]);
                const float h3 = tanh_f(acc[idx+3] + cf[CF_BE1 + c + 1]);
                const float* w0 = &cf[CF_WE2 + c * 6];
                const float* w1 = &cf[CF_WE2 + (c + 1) * 6];
#pragma unroll
                for (int j = 0; j < 6; ++j) {
                    zp[(im*2+0)*6+j] += h0 * w0[j] + h1 * w1[j];
                    zp[(im*2+1)*6+j] += h2 * w0[j] + h3 * w1[j];
                }
            }
#pragma unroll
            for (int i = 0; i < 24; ++i) {
                zp[i] += __shfl_xor_sync(0xffffffffu, zp[i], 1);
                zp[i] += __shfl_xor_sync(0xffffffffu, zp[i], 2);
            }
            if (t == 0) {
#pragma unroll
                for (int im = 0; im < 2; ++im)
#pragma unroll
                for (int rh = 0; rh < 2; ++rh) {
                    const int r = warpM + 16 * im + 8 * rh + g;
#pragma unroll
                    for (int j = 0; j < 6; ++j)
                        cf[CF_ZP + (ngrp * 128 + r) * 6 + j] = zp[(im*2+rh)*6+j];
                }
            }
        }
        __syncthreads();

        // ---- E2 finish + D1: z -> d planes (scalar, tiny) ----
        {
            const int r = tid >> 1;
            const int ih = (tid & 1) * 64;
            float z[6];
#pragma unroll
            for (int j = 0; j < 6; ++j)
                z[j] = tanh_f(cf[CF_ZP + r * 6 + j] + cf[CF_ZP + 768 + r * 6 + j]
                              + cf[CF_BE2 + j]);
#pragma unroll 8
            for (int i = ih; i < ih + 64; i += 2) {
                float d0 = cf[CF_BD1 + i], d1 = cf[CF_BD1 + i + 1];
#pragma unroll
                for (int j = 0; j < 6; ++j) {
                    d0 = fmaf(z[j], cf[CF_WD1 + j * 128 + i],     d0);
                    d1 = fmaf(z[j], cf[CF_WD1 + j * 128 + i + 1], d1);
                }
                u32 lo; u32 hi = pack_split(tanh_f(d0), tanh_f(d1), lo);
                *(u32*)(smem + SM_A + r * P_D + i * 2) = hi;
                *(u32*)(smem + SM_A + D_LO + r * P_D + i * 2) = lo;
            }
        }
        __syncthreads();

        // ---- D2: [128x128] @ [128x256], K chunked by 64 ----
        {
            float acc[128];
#pragma unroll
            for (int i = 0; i < 128; ++i) acc[i] = 0.f;
            for (int c = 0; c < 2; ++c) {
                cpy16(smem + SM_B, g_Wd2t + c * 73728, 4608, tid);
                __syncthreads();
#pragma unroll
                for (int p = 0; p < 3; ++p)
                    wgemm<4, 8>(acc,
                        sb + SM_A + (p == 1 ? (u32)D_LO : 0u) + warpM * P_D + c * 128, P_D,
                        sb + SM_B + (p == 2 ? (u32)DB_LO : 0u) + wN256 * P_DB, P_DB);
                __syncthreads();
            }
            // epilogue: O-layer row partial sums
            float op[4] = {0.f, 0.f, 0.f, 0.f};
#pragma unroll
            for (int im = 0; im < 2; ++im)
#pragma unroll
            for (int jn = 0; jn < 16; ++jn) {
                const int idx = (im * 16 + jn) * 4;
                const int c = wN256 + 8 * jn + 2 * t;
                op[im*2+0] += tanh_f(acc[idx+0] + cf[CF_BD2 + c])     * cf[CF_WO + c]
                            + tanh_f(acc[idx+1] + cf[CF_BD2 + c + 1]) * cf[CF_WO + c + 1];
                op[im*2+1] += tanh_f(acc[idx+2] + cf[CF_BD2 + c])     * cf[CF_WO + c]
                            + tanh_f(acc[idx+3] + cf[CF_BD2 + c + 1]) * cf[CF_WO + c + 1];
            }
#pragma unroll
            for (int i = 0; i < 4; ++i) {
                op[i] += __shfl_xor_sync(0xffffffffu, op[i], 1);
                op[i] += __shfl_xor_sync(0xffffffffu, op[i], 2);
            }
            if (t == 0) {
#pragma unroll
                for (int im = 0; im < 2; ++im)
#pragma unroll
                for (int rh = 0; rh < 2; ++rh)
                    cf[CF_OP + ngrp * 128 + warpM + 16 * im + 8 * rh + g] = op[im*2+rh];
            }
        }
        __syncthreads();

        if (tid < 128) {
            const float v = cf[CF_OP + tid] + cf[CF_OP + 128 + tid] + cf[CF_BO];
            float e;  asm("ex2.approx.f32 %0, %1;" : "=f"(e)  : "f"(-1.442695041f * v));
            float sg; asm("rcp.approx.f32 %0, %1;" : "=f"(sg) : "f"(1.0f + e));
            if (nb + tid < Nn) out[nb + tid] = sg;
        }
    }
}

// ---------------- launch ----------------
extern "C" void kernel_launch(void* const* d_in, const int* in_sizes, int n_in,
                              void* d_out, int out_size)
{
    // order: x, edge_index, edge_attr, W1, b1, We1, be1, We2, be2,
    //        Wd1, bd1, Wd2, bd2, Wo, bo
    const float* edge_attr = (const float*)d_in[2];
    const float* W1  = (const float*)d_in[3];
    const float* b1  = (const float*)d_in[4];
    const float* We1 = (const float*)d_in[5];
    const float* be1 = (const float*)d_in[6];
    const float* We2 = (const float*)d_in[7];
    const float* be2 = (const float*)d_in[8];
    const float* Wd1 = (const float*)d_in[9];
    const float* bd1 = (const float*)d_in[10];
    const float* Wd2 = (const float*)d_in[11];
    const float* bd2 = (const float*)d_in[12];
    const float* Wo  = (const float*)d_in[13];
    const float* bo  = (const float*)d_in[14];
    float* out = (float*)d_out;

    const int Nn = out_size;
    const int ntiles = (Nn + 127) / 128;

    prep_weights<<<304, 256>>>(W1, We1, Wd2);   // 77824 elements

    cudaFuncSetAttribute(gnn_mma_kernel,
                         cudaFuncAttributeMaxDynamicSharedMemorySize, SMEM_BYTES);
    int sms = 148;
    cudaDeviceGetAttribute(&sms, cudaDevAttrMultiProcessorCount, 0);
    const int grid = ntiles < sms ? ntiles : sms;

    gnn_mma_kernel<<<grid, 256, SMEM_BYTES>>>(
        edge_attr, b1, be1, We2, be2, Wd1, bd1, bd2, Wo, bo, out, Nn, ntiles);
}

// round 13
// speedup vs baseline: 1.2744x; 1.2677x over previous
#include <cuda_runtime.h>
#include <cuda_bf16.h>

typedef unsigned int u32;

// ---------------- pitches (bytes) ----------------
#define P_MS  48     /* msgs / W1t rows: K=16+8 pad  */
#define P_H   528    /* h planes: K=256+8 pad        */
#define P_D   272    /* d planes / E1-B chunk: 128+8 */
#define P_DB  144    /* D2-B chunk: 64+8             */

// ---------------- smem layout (bytes) ----------------
#define SM_A    0
#define H_LO    67584            /* 128*528 */
#define D_LO    34816            /* 128*272 */
#define SM_B    135168
#define MS_HI   (SM_B)
#define MS_LO   (SM_B + 6144)
#define W1_HI   (SM_B + 12288)   /* lo at +12288 inside image */
#define EB_LO   34816            /* E1 chunk lo offset  */
#define DB_LO   36864            /* D2 chunk lo offset  */
#define SM_C    (SM_B + 73728)   /* 208896 */
// const region (float offsets from SM_C)
#define CF_B1   0
#define CF_BE1  256
#define CF_WE2  384
#define CF_BE2  1152
#define CF_WD1  1160
#define CF_BD1  1928
#define CF_BD2  2056
#define CF_WO   2312
#define CF_BO   2568
#define CF_ZP   2572             /* 128 rows x 4 ngroups x 6 = 3072 */
#define CF_OP   CF_ZP            /* OP (128x4) aliases ZP           */
#define CF_TOT  (2572 + 3072)
#define SMEM_BYTES (SM_C + CF_TOT*4)   /* 231,472 <= 232,448 */

// ---------------- pre-split/transposed bf16 weight images ----------------
__device__ __align__(16) unsigned char g_W1t[24576];    // [256n][24k] hi | lo
__device__ __align__(16) unsigned char g_We1t[139264];  // 2 x ([128n][136k] hi | lo)
__device__ __align__(16) unsigned char g_Wd2t[147456];  // 2 x ([256n][72k]  hi | lo)

// ---------------- helpers ----------------
__device__ __forceinline__ u32 smem_u32(const void* p) {
    u32 a;
    asm("{ .reg .u64 t; cvta.to.shared.u64 t, %1; cvt.u32.u64 %0, t; }"
        : "=r"(a) : "l"(p));
    return a;
}
__device__ __forceinline__ void ldmx4(u32& r0, u32& r1, u32& r2, u32& r3, u32 addr) {
    asm volatile("ldmatrix.sync.aligned.m8n8.x4.shared.b16 {%0,%1,%2,%3}, [%4];"
                 : "=r"(r0), "=r"(r1), "=r"(r2), "=r"(r3) : "r"(addr));
}
__device__ __forceinline__ void mma16816(float* c, u32 a0, u32 a1, u32 a2, u32 a3,
                                         u32 b0, u32 b1) {
    asm volatile("mma.sync.aligned.m16n8k16.row.col.f32.bf16.bf16.f32 "
                 "{%0,%1,%2,%3}, {%4,%5,%6,%7}, {%8,%9}, {%0,%1,%2,%3};"
                 : "+f"(c[0]), "+f"(c[1]), "+f"(c[2]), "+f"(c[3])
                 : "r"(a0), "r"(a1), "r"(a2), "r"(a3), "r"(b0), "r"(b1));
}
__device__ __forceinline__ float tanh_f(float x) {
    float e; asm("ex2.approx.f32 %0, %1;" : "=f"(e) : "f"(x * 2.885390082f));
    float r; asm("rcp.approx.f32 %0, %1;" : "=f"(r) : "f"(e + 1.0f));
    return fmaf(-2.0f, r, 1.0f);
}
__device__ __forceinline__ u32 pack_split(float x0, float x1, u32& lo) {
    __nv_bfloat16 h0 = __float2bfloat16(x0), h1 = __float2bfloat16(x1);
    __nv_bfloat16 l0 = __float2bfloat16(x0 - __bfloat162float(h0));
    __nv_bfloat16 l1 = __float2bfloat16(x1 - __bfloat162float(h1));
    lo = (u32)__bfloat16_as_ushort(l0) | ((u32)__bfloat16_as_ushort(l1) << 16);
    return (u32)__bfloat16_as_ushort(h0) | ((u32)__bfloat16_as_ushort(h1) << 16);
}
__device__ __forceinline__ void wsplit(unsigned char* hi, unsigned char* lo, float v) {
    __nv_bfloat16 h = __float2bfloat16(v);
    __nv_bfloat16 l = __float2bfloat16(v - __bfloat162float(h));
    *(__nv_bfloat16*)hi = h;
    *(__nv_bfloat16*)lo = l;
}

// ---------------- prep: transpose + split weights into smem-image layout ----
__global__ void prep_weights(const float* __restrict__ W1,
                             const float* __restrict__ We1,
                             const float* __restrict__ Wd2)
{
    int idx = blockIdx.x * 256 + threadIdx.x;
    if (idx < 6144) {                              // W1t: [256n][24k]
        int n = idx / 24, k = idx % 24;
        float v = (k < 16) ? W1[k * 256 + n] : 0.f;
        wsplit(g_W1t + n * P_MS + k * 2, g_W1t + 12288 + n * P_MS + k * 2, v);
        return;
    }
    idx -= 6144;
    if (idx < 34816) {                             // We1t: 2 x [128n][136k]
        int c = idx / 17408, rst = idx % 17408;
        int n = rst / 136, kk = rst % 136;
        float v = (kk < 128) ? We1[(c * 128 + kk) * 128 + n] : 0.f;
        int base = c * 69632 + n * P_D + kk * 2;
        wsplit(g_We1t + base, g_We1t + base + EB_LO, v);
        return;
    }
    idx -= 34816;
    if (idx < 36864) {                             // Wd2t: 2 x [256n][72k]
        int c = idx / 18432, rst = idx % 18432;
        int n = rst / 72, kk = rst % 72;
        float v = (kk < 64) ? Wd2[(c * 64 + kk) * 256 + n] : 0.f;
        int base = c * 73728 + n * P_DB + kk * 2;
        wsplit(g_Wd2t + base, g_Wd2t + base + DB_LO, v);
    }
}

// ------ merged 3-pass warp GEMM: 32 rows x (NPAIRS*16) cols, hi/lo planes ----
// per k16 step: load Ahi,Alo (2+2 ldmx4), per np load Bhi,Blo (2 ldmx4),
// issue hh + lh + hl MMAs from the same fragments.
template<int KSTEPS, int NPAIRS>
__device__ __forceinline__ void wgemm3(float* acc, u32 aBase, u32 aLoOff, int aPitch,
                                       u32 bBase, u32 bLoOff, int bPitch)
{
    const int lane = threadIdx.x & 31;
    const u32 aAddr = aBase + (u32)((lane & 15) * aPitch + ((lane >> 4) << 4));
    const int q = lane >> 3;
    const u32 bAddr = bBase + (u32)((((q >> 1) << 3) + (lane & 7)) * bPitch
                                    + ((q & 1) << 4));
#pragma unroll
    for (int ks = 0; ks < KSTEPS; ++ks) {
        u32 ah[8], al[8];
        ldmx4(ah[0], ah[1], ah[2], ah[3], aAddr + ks * 32);
        ldmx4(ah[4], ah[5], ah[6], ah[7], aAddr + 16 * aPitch + ks * 32);
        ldmx4(al[0], al[1], al[2], al[3], aAddr + aLoOff + ks * 32);
        ldmx4(al[4], al[5], al[6], al[7], aAddr + aLoOff + 16 * aPitch + ks * 32);
#pragma unroll
        for (int np = 0; np < NPAIRS; ++np) {
            u32 bh0, bh1, bh2, bh3, bl0, bl1, bl2, bl3;
            ldmx4(bh0, bh1, bh2, bh3, bAddr + np * 16 * bPitch + ks * 32);
            ldmx4(bl0, bl1, bl2, bl3, bAddr + bLoOff + np * 16 * bPitch + ks * 32);
#pragma unroll
            for (int im = 0; im < 2; ++im) {
                float* c0 = acc + (im * 2 * NPAIRS + 2 * np + 0) * 4;
                float* c1 = acc + (im * 2 * NPAIRS + 2 * np + 1) * 4;
                const u32* A = ah + im * 4;
                const u32* L = al + im * 4;
                mma16816(c0, A[0], A[1], A[2], A[3], bh0, bh1);
                mma16816(c0, L[0], L[1], L[2], L[3], bh0, bh1);
                mma16816(c0, A[0], A[1], A[2], A[3], bl0, bl1);
                mma16816(c1, A[0], A[1], A[2], A[3], bh2, bh3);
                mma16816(c1, L[0], L[1], L[2], L[3], bh2, bh3);
                mma16816(c1, A[0], A[1], A[2], A[3], bl2, bl3);
            }
        }
    }
}

__device__ __forceinline__ void cpy16(unsigned char* dst, const unsigned char* src,
                                      int n16, int tid, int nthr)
{
    const uint4* s = (const uint4*)src;
    uint4* d = (uint4*)dst;
    for (int i = tid; i < n16; i += nthr) d[i] = s[i];
}

// ---------------- main fused kernel (512 threads, 16 warps) ----------------
__global__ void __launch_bounds__(512, 1)
gnn_mma_kernel(const float* __restrict__ edge_attr,
               const float* __restrict__ b1,  const float* __restrict__ be1,
               const float* __restrict__ We2, const float* __restrict__ be2,
               const float* __restrict__ Wd1, const float* __restrict__ bd1,
               const float* __restrict__ bd2, const float* __restrict__ Wo,
               const float* __restrict__ bo,
               float* __restrict__ out, int Nn, int ntiles)
{
    extern __shared__ unsigned char smem[];
    float* cf = (float*)(smem + SM_C);
    const int tid = threadIdx.x;
    const int w = tid >> 5, lane = tid & 31;
    const int g = lane >> 2, t = lane & 3;
    const int warpM = (w & 3) * 32;      // m-group
    const int ng = w >> 2;               // n-group 0..3
    const u32 sb = smem_u32(smem);

    // constants (once per block) — ALL ranges covered by strided loops
    if (tid < 256) cf[CF_B1 + tid] = b1[tid];
    if (tid < 128) cf[CF_BE1 + tid] = be1[tid];
    for (int i = tid; i < 768; i += 512) cf[CF_WE2 + i] = We2[i];   // FIX: full 768
    if (tid < 6)   cf[CF_BE2 + tid] = be2[tid];
    {
        int i = tid - 256;
        if (i >= 0 && i < 256) { cf[CF_BD2 + i] = bd2[i]; cf[CF_WO + i] = Wo[i]; }
    }
    if (tid >= 384 && tid < 512) cf[CF_BD1 + tid - 384] = bd1[tid - 384];
    for (int i = tid; i < 768; i += 512) cf[CF_WD1 + i] = Wd1[i];
    if (tid == 0)  cf[CF_BO] = bo[0];

    for (int tile = blockIdx.x; tile < ntiles; tile += gridDim.x) {
        const int nb = tile * 128;
        __syncthreads();                          // prev tile fully consumed

        // ---- stage msgs (split planes) + W1t image ----
        if (tid < 128) {
            float f[16];
            const int node = nb + tid;
            if (node < Nn) {
                const float4* p = (const float4*)(edge_attr + (size_t)node * 16);
#pragma unroll
                for (int q4 = 0; q4 < 4; ++q4) {
                    float4 v = p[q4];
                    f[4*q4+0]=v.x; f[4*q4+1]=v.y; f[4*q4+2]=v.z; f[4*q4+3]=v.w;
                }
            } else {
#pragma unroll
                for (int i = 0; i < 16; ++i) f[i] = 0.f;
            }
#pragma unroll
            for (int kp = 0; kp < 8; ++kp) {
                u32 lo; u32 hi = pack_split(f[2*kp], f[2*kp+1], lo);
                *(u32*)(smem + MS_HI + tid * P_MS + kp * 4) = hi;
                *(u32*)(smem + MS_LO + tid * P_MS + kp * 4) = lo;
            }
        }
        cpy16(smem + W1_HI, g_W1t, 1536, tid, 512);
        __syncthreads();

        // ---- L1: [128x16] @ [16x256] -> h planes (warp tile 32m x 64n) ----
        {
            float acc[64];
#pragma unroll
            for (int i = 0; i < 64; ++i) acc[i] = 0.f;
            wgemm3<1, 4>(acc, sb + MS_HI + warpM * P_MS, 6144u, P_MS,
                              sb + W1_HI + ng * 64 * P_MS, 12288u, P_MS);
            const int wN = ng * 64;
#pragma unroll
            for (int im = 0; im < 2; ++im)
#pragma unroll
            for (int jn = 0; jn < 8; ++jn) {
                const int idx = (im * 8 + jn) * 4;
                const int c = wN + 8 * jn + 2 * t;
                const int r = warpM + 16 * im + g;
                u32 lo;
                u32 hi = pack_split(tanh_f(acc[idx+0] + cf[CF_B1 + c]),
                                    tanh_f(acc[idx+1] + cf[CF_B1 + c + 1]), lo);
                *(u32*)(smem + SM_A + r * P_H + c * 2) = hi;
                *(u32*)(smem + SM_A + H_LO + r * P_H + c * 2) = lo;
                hi = pack_split(tanh_f(acc[idx+2] + cf[CF_B1 + c]),
                                tanh_f(acc[idx+3] + cf[CF_B1 + c + 1]), lo);
                *(u32*)(smem + SM_A + (r + 8) * P_H + c * 2) = hi;
                *(u32*)(smem + SM_A + H_LO + (r + 8) * P_H + c * 2) = lo;
            }
        }
        __syncthreads();                       // h ready; SM_B reads done

        // ---- E1: [128x256] @ [256x128] (warp tile 32m x 32n), 2 K-chunks ----
        {
            float acc[32];
#pragma unroll
            for (int i = 0; i < 32; ++i) acc[i] = 0.f;
            for (int c = 0; c < 2; ++c) {
                cpy16(smem + SM_B, g_We1t + c * 69632, 4352, tid, 512);
                __syncthreads();
                wgemm3<8, 2>(acc, sb + SM_A + warpM * P_H + c * 256, (u32)H_LO, P_H,
                                  sb + SM_B + ng * 32 * P_D, (u32)EB_LO, P_D);
                __syncthreads();
            }
            // epilogue: tanh -> E2 partials (z) per n-group
            float zp[24];
#pragma unroll
            for (int i = 0; i < 24; ++i) zp[i] = 0.f;
            const int wN = ng * 32;
#pragma unroll
            for (int im = 0; im < 2; ++im)
#pragma unroll
            for (int jn = 0; jn < 4; ++jn) {
                const int idx = (im * 4 + jn) * 4;
                const int c = wN + 8 * jn + 2 * t;
                const float h0 = tanh_f(acc[idx+0] + cf[CF_BE1 + c]);
                const float h1 = tanh_f(acc[idx+1] + cf[CF_BE1 + c + 1]);
                const float h2 = tanh_f(acc[idx+2] + cf[CF_BE1 + c]);
                const float h3 = tanh_f(acc[idx+3] + cf[CF_BE1 + c + 1]);
                const float* w0 = &cf[CF_WE2 + c * 6];
                const float* w1 = &cf[CF_WE2 + (c + 1) * 6];
#pragma unroll
                for (int j = 0; j < 6; ++j) {
                    zp[(im*2+0)*6+j] += h0 * w0[j] + h1 * w1[j];
                    zp[(im*2+1)*6+j] += h2 * w0[j] + h3 * w1[j];
                }
            }
#pragma unroll
            for (int i = 0; i < 24; ++i) {
                zp[i] += __shfl_xor_sync(0xffffffffu, zp[i], 1);
                zp[i] += __shfl_xor_sync(0xffffffffu, zp[i], 2);
            }
            if (t == 0) {
#pragma unroll
                for (int im = 0; im < 2; ++im)
#pragma unroll
                for (int rh = 0; rh < 2; ++rh) {
                    const int r = warpM + 16 * im + 8 * rh + g;
#pragma unroll
                    for (int j = 0; j < 6; ++j)
                        cf[CF_ZP + ng * 768 + r * 6 + j] = zp[(im*2+rh)*6+j];
                }
            }
        }
        __syncthreads();                       // ZP ready

        // ---- E2 finish + D1 (threads 0-255) || stage D2 chunk0 (256-511) ----
        if (tid >= 256) {
            cpy16(smem + SM_B, g_Wd2t, 4608, tid - 256, 256);
        } else {
            const int r = tid >> 1;
            const int ih = (tid & 1) * 64;
            float z[6];
#pragma unroll
            for (int j = 0; j < 6; ++j)
                z[j] = tanh_f(cf[CF_ZP + r*6 + j]       + cf[CF_ZP + 768 + r*6 + j]
                            + cf[CF_ZP + 1536 + r*6 + j] + cf[CF_ZP + 2304 + r*6 + j]
                            + cf[CF_BE2 + j]);
#pragma unroll 8
            for (int i = ih; i < ih + 64; i += 2) {
                float d0 = cf[CF_BD1 + i], d1 = cf[CF_BD1 + i + 1];
#pragma unroll
                for (int j = 0; j < 6; ++j) {
                    d0 = fmaf(z[j], cf[CF_WD1 + j * 128 + i],     d0);
                    d1 = fmaf(z[j], cf[CF_WD1 + j * 128 + i + 1], d1);
                }
                u32 lo; u32 hi = pack_split(tanh_f(d0), tanh_f(d1), lo);
                *(u32*)(smem + SM_A + r * P_D + i * 2) = hi;
                *(u32*)(smem + SM_A + D_LO + r * P_D + i * 2) = lo;
            }
        }
        __syncthreads();                       // d planes + D2 chunk0 ready

        // ---- D2: [128x128] @ [128x256] (warp tile 32m x 64n), 2 K-chunks ----
        {
            float acc[64];
#pragma unroll
            for (int i = 0; i < 64; ++i) acc[i] = 0.f;
            for (int c = 0; c < 2; ++c) {
                if (c) {
                    cpy16(smem + SM_B, g_Wd2t + 73728, 4608, tid, 512);
                    __syncthreads();
                }
                wgemm3<4, 4>(acc, sb + SM_A + warpM * P_D + c * 128, (u32)D_LO, P_D,
                                  sb + SM_B + ng * 64 * P_DB, (u32)DB_LO, P_DB);
                __syncthreads();
            }
            // epilogue: O-layer partial row sums per n-group
            float op[4] = {0.f, 0.f, 0.f, 0.f};
            const int wN = ng * 64;
#pragma unroll
            for (int im = 0; im < 2; ++im)
#pragma unroll
            for (int jn = 0; jn < 8; ++jn) {
                const int idx = (im * 8 + jn) * 4;
                const int c = wN + 8 * jn + 2 * t;
                op[im*2+0] += tanh_f(acc[idx+0] + cf[CF_BD2 + c])     * cf[CF_WO + c]
                            + tanh_f(acc[idx+1] + cf[CF_BD2 + c + 1]) * cf[CF_WO + c + 1];
                op[im*2+1] += tanh_f(acc[idx+2] + cf[CF_BD2 + c])     * cf[CF_WO + c]
                            + tanh_f(acc[idx+3] + cf[CF_BD2 + c + 1]) * cf[CF_WO + c + 1];
            }
#pragma unroll
            for (int i = 0; i < 4; ++i) {
                op[i] += __shfl_xor_sync(0xffffffffu, op[i], 1);
                op[i] += __shfl_xor_sync(0xffffffffu, op[i], 2);
            }
            if (t == 0) {
#pragma unroll
                for (int im = 0; im < 2; ++im)
#pragma unroll
                for (int rh = 0; rh < 2; ++rh)
                    cf[CF_OP + ng * 128 + warpM + 16 * im + 8 * rh + g] = op[im*2+rh];
            }
        }
        __syncthreads();

        if (tid < 128) {
            const float v = cf[CF_OP + tid] + cf[CF_OP + 128 + tid]
                          + cf[CF_OP + 256 + tid] + cf[CF_OP + 384 + tid] + cf[CF_BO];
            float e;  asm("ex2.approx.f32 %0, %1;" : "=f"(e)  : "f"(-1.442695041f * v));
            float sg; asm("rcp.approx.f32 %0, %1;" : "=f"(sg) : "f"(1.0f + e));
            if (nb + tid < Nn) out[nb + tid] = sg;
        }
    }
}

// ---------------- launch ----------------
extern "C" void kernel_launch(void* const* d_in, const int* in_sizes, int n_in,
                              void* d_out, int out_size)
{
    // order: x, edge_index, edge_attr, W1, b1, We1, be1, We2, be2,
    //        Wd1, bd1, Wd2, bd2, Wo, bo
    const float* edge_attr = (const float*)d_in[2];
    const float* W1  = (const float*)d_in[3];
    const float* b1  = (const float*)d_in[4];
    const float* We1 = (const float*)d_in[5];
    const float* be1 = (const float*)d_in[6];
    const float* We2 = (const float*)d_in[7];
    const float* be2 = (const float*)d_in[8];
    const float* Wd1 = (const float*)d_in[9];
    const float* bd1 = (const float*)d_in[10];
    const float* Wd2 = (const float*)d_in[11];
    const float* bd2 = (const float*)d_in[12];
    const float* Wo  = (const float*)d_in[13];
    const float* bo  = (const float*)d_in[14];
    float* out = (float*)d_out;

    const int Nn = out_size;
    const int ntiles = (Nn + 127) / 128;

    prep_weights<<<304, 256>>>(W1, We1, Wd2);

    cudaFuncSetAttribute(gnn_mma_kernel,
                         cudaFuncAttributeMaxDynamicSharedMemorySize, SMEM_BYTES);
    int sms = 148;
    cudaDeviceGetAttribute(&sms, cudaDevAttrMultiProcessorCount, 0);
    const int grid = ntiles < sms ? ntiles : sms;

    gnn_mma_kernel<<<grid, 512, SMEM_BYTES>>>(
        edge_attr, b1, be1, We2, be2, Wd1, bd1, bd2, Wo, bo, out, Nn, ntiles);
}

// round 14
// speedup vs baseline: 1.4505x; 1.1382x over previous
#include <cuda_runtime.h>
#include <cuda_fp16.h>

typedef unsigned int u32;

// ---------------- pitches (bytes) ----------------
#define P_MS  48     /* msgs / W1t rows: K=16+8 pad  */
#define P_H   528    /* h planes / We1 rows: 256+8   */
#define P_D   272    /* d planes / Wd2 rows: 128+8   */

// ---------------- smem layout (bytes) ----------------
#define SM_A    0                /* 135168: h planes 2x67584 / d planes / scratch */
#define H_LOF   67584            /* h lo-plane offset  */
#define D_LOF   34816            /* d lo-plane offset  */
#define MS_HI   0                /* msgs hi: 128*48            (L1 phase)  */
#define MS_LO   6144             /* msgs lo                                 */
#define W1T     12288            /* W1t single plane: 12288    (L1 phase)  */
#define RAWBUF  73728            /* next-tile raw edge_attr: 8192 (D2 phase)*/
#define SM_B    135168           /* 73728: We1 (67584) then Wd2 (69632)     */
#define SM_C    (SM_B + 73728)   /* 208896 */
// const region (float offsets from SM_C)
#define CF_B1   0
#define CF_BE1  256
#define CF_WE2  384
#define CF_BE2  1152
#define CF_WD1  1160
#define CF_BD1  1928
#define CF_BD2  2056
#define CF_WO   2312
#define CF_BO   2568
#define CF_ZP   2572             /* 4 ngroups x 128 x 6 = 3072 */
#define CF_OP   CF_ZP            /* OP (4x128) aliases ZP      */
#define CF_TOT  (2572 + 3072)
#define SMEM_BYTES (SM_C + CF_TOT*4)   /* 231,472 <= 232,448 */

// ---------------- pre-transposed single-plane fp16 weight images ------------
__device__ __align__(16) unsigned char g_W1t[12288];   // [256n][24k]
__device__ __align__(16) unsigned char g_We1t[67584];  // [128n][264k]
__device__ __align__(16) unsigned char g_Wd2t[69632];  // [256n][136k]

// ---------------- helpers ----------------
__device__ __forceinline__ u32 smem_u32(const void* p) {
    u32 a;
    asm("{ .reg .u64 t; cvta.to.shared.u64 t, %1; cvt.u32.u64 %0, t; }"
        : "=r"(a) : "l"(p));
    return a;
}
__device__ __forceinline__ void ldmx4(u32& r0, u32& r1, u32& r2, u32& r3, u32 addr) {
    asm volatile("ldmatrix.sync.aligned.m8n8.x4.shared.b16 {%0,%1,%2,%3}, [%4];"
                 : "=r"(r0), "=r"(r1), "=r"(r2), "=r"(r3) : "r"(addr));
}
__device__ __forceinline__ void mmah(float* c, u32 a0, u32 a1, u32 a2, u32 a3,
                                     u32 b0, u32 b1) {
    asm volatile("mma.sync.aligned.m16n8k16.row.col.f32.f16.f16.f32 "
                 "{%0,%1,%2,%3}, {%4,%5,%6,%7}, {%8,%9}, {%0,%1,%2,%3};"
                 : "+f"(c[0]), "+f"(c[1]), "+f"(c[2]), "+f"(c[3])
                 : "r"(a0), "r"(a1), "r"(a2), "r"(a3), "r"(b0), "r"(b1));
}
__device__ __forceinline__ float tanh_f(float x) {
    float e; asm("ex2.approx.f32 %0, %1;" : "=f"(e) : "f"(x * 2.885390082f));
    float r; asm("rcp.approx.f32 %0, %1;" : "=f"(r) : "f"(e + 1.0f));
    return fmaf(-2.0f, r, 1.0f);
}
// fp16 two-word split of a pair of floats
__device__ __forceinline__ u32 pack_split_h(float x0, float x1, u32& lo) {
    __half h0 = __float2half_rn(x0), h1 = __float2half_rn(x1);
    __half l0 = __float2half_rn(x0 - __half2float(h0));
    __half l1 = __float2half_rn(x1 - __half2float(h1));
    lo = (u32)__half_as_ushort(l0) | ((u32)__half_as_ushort(l1) << 16);
    return (u32)__half_as_ushort(h0) | ((u32)__half_as_ushort(h1) << 16);
}
// cp.async
__device__ __forceinline__ void cpa(u32 dst, const void* src) {
    asm volatile("cp.async.cg.shared.global [%0], [%1], 16;" :: "r"(dst), "l"(src));
}
__device__ __forceinline__ void cpa_g(u32 dst, const void* src, int ss) {
    asm volatile("cp.async.cg.shared.global [%0], [%1], 16, %2;"
                 :: "r"(dst), "l"(src), "r"(ss));
}
#define CP_COMMIT() asm volatile("cp.async.commit_group;" ::: "memory")
#define CP_WAIT(N)  asm volatile("cp.async.wait_group %0;" :: "n"(N) : "memory")

// ---------------- prep: transpose weights to fp16 images -------------------
__global__ void prep_weights(const float* __restrict__ W1,
                             const float* __restrict__ We1,
                             const float* __restrict__ Wd2)
{
    int idx = blockIdx.x * 256 + threadIdx.x;
    if (idx < 6144) {                              // W1t [256n][24k]
        int n = idx / 24, k = idx % 24;
        float v = (k < 16) ? W1[k * 256 + n] : 0.f;
        *(__half*)(g_W1t + n * P_MS + k * 2) = __float2half_rn(v);
        return;
    }
    idx -= 6144;
    if (idx < 33792) {                             // We1t [128n][264k]
        int n = idx / 264, kk = idx % 264;
        float v = (kk < 256) ? We1[kk * 128 + n] : 0.f;
        *(__half*)(g_We1t + n * P_H + kk * 2) = __float2half_rn(v);
        return;
    }
    idx -= 33792;
    if (idx < 34816) {                             // Wd2t [256n][136k]
        int n = idx / 136, kk = idx % 136;
        float v = (kk < 128) ? Wd2[kk * 256 + n] : 0.f;
        *(__half*)(g_Wd2t + n * P_D + kk * 2) = __float2half_rn(v);
    }
}

// ------ 2-pass warp GEMM: A hi/lo fp16 planes, B single fp16 plane ---------
template<int KSTEPS, int NPAIRS>
__device__ __forceinline__ void wgemm2(float* acc, u32 aBase, u32 aLoOff, int aPitch,
                                       u32 bBase, int bPitch)
{
    const int lane = threadIdx.x & 31;
    const u32 aAddr = aBase + (u32)((lane & 15) * aPitch + ((lane >> 4) << 4));
    const int q = lane >> 3;
    const u32 bAddr = bBase + (u32)((((q >> 1) << 3) + (lane & 7)) * bPitch
                                    + ((q & 1) << 4));
#pragma unroll
    for (int ks = 0; ks < KSTEPS; ++ks) {
        u32 ah[8], al[8];
        ldmx4(ah[0], ah[1], ah[2], ah[3], aAddr + ks * 32);
        ldmx4(ah[4], ah[5], ah[6], ah[7], aAddr + 16 * aPitch + ks * 32);
        ldmx4(al[0], al[1], al[2], al[3], aAddr + aLoOff + ks * 32);
        ldmx4(al[4], al[5], al[6], al[7], aAddr + aLoOff + 16 * aPitch + ks * 32);
#pragma unroll
        for (int np = 0; np < NPAIRS; ++np) {
            u32 b0, b1, b2, b3;
            ldmx4(b0, b1, b2, b3, bAddr + np * 16 * bPitch + ks * 32);
#pragma unroll
            for (int im = 0; im < 2; ++im) {
                float* c0 = acc + (im * 2 * NPAIRS + 2 * np + 0) * 4;
                float* c1 = acc + (im * 2 * NPAIRS + 2 * np + 1) * 4;
                const u32* A = ah + im * 4;
                const u32* L = al + im * 4;
                mmah(c0, A[0], A[1], A[2], A[3], b0, b1);
                mmah(c0, L[0], L[1], L[2], L[3], b0, b1);
                mmah(c1, A[0], A[1], A[2], A[3], b2, b3);
                mmah(c1, L[0], L[1], L[2], L[3], b2, b3);
            }
        }
    }
}

// ---------------- main fused kernel (512 threads, 16 warps) ----------------
__global__ void __launch_bounds__(512, 1)
gnn_mma_kernel(const float* __restrict__ edge_attr,
               const float* __restrict__ b1,  const float* __restrict__ be1,
               const float* __restrict__ We2, const float* __restrict__ be2,
               const float* __restrict__ Wd1, const float* __restrict__ bd1,
               const float* __restrict__ bd2, const float* __restrict__ Wo,
               const float* __restrict__ bo,
               float* __restrict__ out, int Nn, int ntiles)
{
    extern __shared__ unsigned char smem[];
    float* cf = (float*)(smem + SM_C);
    const int tid = threadIdx.x;
    const int w = tid >> 5, lane = tid & 31;
    const int g = lane >> 2, t = lane & 3;
    const int warpM = (w & 3) * 32;      // m-group 0..3
    const int ng = w >> 2;               // n-group 0..3
    const u32 sb = smem_u32(smem);

    // constants (strided loops cover full ranges at 512 threads)
    if (tid < 256) cf[CF_B1 + tid] = b1[tid];
    if (tid < 128) cf[CF_BE1 + tid] = be1[tid];
    for (int i = tid; i < 768; i += 512) cf[CF_WE2 + i] = We2[i];
    if (tid < 6)   cf[CF_BE2 + tid] = be2[tid];
    {
        int i = tid - 256;
        if (i >= 0 && i < 256) { cf[CF_BD2 + i] = bd2[i]; cf[CF_WO + i] = Wo[i]; }
    }
    if (tid >= 384 && tid < 512) cf[CF_BD1 + tid - 384] = bd1[tid - 384];
    for (int i = tid; i < 768; i += 512) cf[CF_WD1 + i] = Wd1[i];
    if (tid == 0)  cf[CF_BO] = bo[0];

    // prologue: prefetch first tile's raw edge_attr (512 x 16B = 8KB)
    {
        const int nb0 = blockIdx.x * 128;
        const int node = tid >> 2;
        cpa_g(sb + RAWBUF + tid * 16,
              edge_attr + (size_t)nb0 * 16 + tid * 4,
              (nb0 + node < Nn) ? 16 : 0);
        CP_COMMIT();                          // group: raw(t0)
    }

    for (int tile = blockIdx.x; tile < ntiles; tile += gridDim.x) {
        const int nb = tile * 128;
        CP_WAIT(0);                           // raw msgs landed
        __syncthreads();                      // visible; prev-tile smem reads done

        // issue weight copies for this tile
        for (int i = tid; i < 768; i += 512)   cpa(sb + W1T + i * 16, g_W1t + i * 16);
        CP_COMMIT();                          // group A: W1t
        for (int i = tid; i < 4224; i += 512)  cpa(sb + SM_B + i * 16, g_We1t + i * 16);
        CP_COMMIT();                          // group B: We1

        // transform raw -> msgs hi/lo fp16 planes
        {
            const int node = tid >> 2;
            const float* rp = (const float*)(smem + RAWBUF) + node * 16 + (t) * 4;
            const float v0 = rp[0], v1 = rp[1], v2 = rp[2], v3 = rp[3];
            u32 lo0, lo1;
            const u32 hi0 = pack_split_h(v0, v1, lo0);
            const u32 hi1 = pack_split_h(v2, v3, lo1);
            const int p4 = (tid & 3) * 8;     // byte offset of k-pair group
            *(u32*)(smem + MS_HI + node * P_MS + p4)     = hi0;
            *(u32*)(smem + MS_HI + node * P_MS + p4 + 4) = hi1;
            *(u32*)(smem + MS_LO + node * P_MS + p4)     = lo0;
            *(u32*)(smem + MS_LO + node * P_MS + p4 + 4) = lo1;
        }
        CP_WAIT(1);                           // W1t done (We1 may pend)
        __syncthreads();

        // ---- L1: [128x16] @ [16x256] (warp 32m x 64n) ----
        float accL[64];
#pragma unroll
        for (int i = 0; i < 64; ++i) accL[i] = 0.f;
        wgemm2<1, 4>(accL, sb + MS_HI + warpM * P_MS, 6144u, P_MS,
                           sb + W1T + ng * 64 * P_MS, P_MS);
        __syncthreads();                      // all gemm reads of SM_A done
        {
            const int wN = ng * 64;
#pragma unroll
            for (int im = 0; im < 2; ++im)
#pragma unroll
            for (int jn = 0; jn < 8; ++jn) {
                const int idx = (im * 8 + jn) * 4;
                const int c = wN + 8 * jn + 2 * t;
                const int r = warpM + 16 * im + g;
                u32 lo;
                u32 hi = pack_split_h(tanh_f(accL[idx+0] + cf[CF_B1 + c]),
                                      tanh_f(accL[idx+1] + cf[CF_B1 + c + 1]), lo);
                *(u32*)(smem + SM_A + r * P_H + c * 2) = hi;
                *(u32*)(smem + SM_A + H_LOF + r * P_H + c * 2) = lo;
                hi = pack_split_h(tanh_f(accL[idx+2] + cf[CF_B1 + c]),
                                  tanh_f(accL[idx+3] + cf[CF_B1 + c + 1]), lo);
                *(u32*)(smem + SM_A + (r + 8) * P_H + c * 2) = hi;
                *(u32*)(smem + SM_A + H_LOF + (r + 8) * P_H + c * 2) = lo;
            }
        }
        CP_WAIT(0);                           // We1 ready
        __syncthreads();                      // h planes visible

        // ---- E1: [128x256] @ [256x128] (warp 32m x 32n), no chunking ----
        {
            float acc[32];
#pragma unroll
            for (int i = 0; i < 32; ++i) acc[i] = 0.f;
            wgemm2<16, 2>(acc, sb + SM_A + warpM * P_H, (u32)H_LOF, P_H,
                               sb + SM_B + ng * 32 * P_H, P_H);
            // epilogue: tanh -> E2 partials per n-group
            float zp[24];
#pragma unroll
            for (int i = 0; i < 24; ++i) zp[i] = 0.f;
            const int wN = ng * 32;
#pragma unroll
            for (int im = 0; im < 2; ++im)
#pragma unroll
            for (int jn = 0; jn < 4; ++jn) {
                const int idx = (im * 4 + jn) * 4;
                const int c = wN + 8 * jn + 2 * t;
                const float h0 = tanh_f(acc[idx+0] + cf[CF_BE1 + c]);
                const float h1 = tanh_f(acc[idx+1] + cf[CF_BE1 + c + 1]);
                const float h2 = tanh_f(acc[idx+2] + cf[CF_BE1 + c]);
                const float h3 = tanh_f(acc[idx+3] + cf[CF_BE1 + c + 1]);
                const float* w0 = &cf[CF_WE2 + c * 6];
                const float* w1 = &cf[CF_WE2 + (c + 1) * 6];
#pragma unroll
                for (int j = 0; j < 6; ++j) {
                    zp[(im*2+0)*6+j] += h0 * w0[j] + h1 * w1[j];
                    zp[(im*2+1)*6+j] += h2 * w0[j] + h3 * w1[j];
                }
            }
#pragma unroll
            for (int i = 0; i < 24; ++i) {
                zp[i] += __shfl_xor_sync(0xffffffffu, zp[i], 1);
                zp[i] += __shfl_xor_sync(0xffffffffu, zp[i], 2);
            }
            if (t == 0) {
#pragma unroll
                for (int im = 0; im < 2; ++im)
#pragma unroll
                for (int rh = 0; rh < 2; ++rh) {
                    const int r = warpM + 16 * im + 8 * rh + g;
#pragma unroll
                    for (int j = 0; j < 6; ++j)
                        cf[CF_ZP + ng * 768 + r * 6 + j] = zp[(im*2+rh)*6+j];
                }
            }
        }
        __syncthreads();                      // ZP visible; SM_A/SM_B reads done

        // issue Wd2 copy (overlaps E2/D1 scalar phase)
        for (int i = tid; i < 4352; i += 512) cpa(sb + SM_B + i * 16, g_Wd2t + i * 16);
        CP_COMMIT();                          // group C: Wd2

        // ---- E2 finish + D1 -> d planes (all 512 threads) ----
        {
            const int r = tid >> 2;
            const int ih = (tid & 3) * 32;
            float z[6];
#pragma unroll
            for (int j = 0; j < 6; ++j)
                z[j] = tanh_f(cf[CF_ZP + r*6 + j]        + cf[CF_ZP + 768 + r*6 + j]
                            + cf[CF_ZP + 1536 + r*6 + j] + cf[CF_ZP + 2304 + r*6 + j]
                            + cf[CF_BE2 + j]);
#pragma unroll 4
            for (int i = ih; i < ih + 32; i += 2) {
                float d0 = cf[CF_BD1 + i], d1 = cf[CF_BD1 + i + 1];
#pragma unroll
                for (int j = 0; j < 6; ++j) {
                    d0 = fmaf(z[j], cf[CF_WD1 + j * 128 + i],     d0);
                    d1 = fmaf(z[j], cf[CF_WD1 + j * 128 + i + 1], d1);
                }
                u32 lo; u32 hi = pack_split_h(tanh_f(d0), tanh_f(d1), lo);
                *(u32*)(smem + SM_A + r * P_D + i * 2) = hi;
                *(u32*)(smem + SM_A + D_LOF + r * P_D + i * 2) = lo;
            }
        }

        // prefetch next tile's raw msgs (overlaps D2)
        {
            const int nb2 = (tile + gridDim.x) * 128;
            const int node = tid >> 2;
            cpa_g(sb + RAWBUF + tid * 16,
                  edge_attr + (size_t)nb2 * 16 + tid * 4,
                  (nb2 + node < Nn) ? 16 : 0);
            CP_COMMIT();                      // group D: raw(t+1)
        }
        CP_WAIT(1);                           // Wd2 done (raw may pend)
        __syncthreads();                      // d planes visible

        // ---- D2: [128x128] @ [128x256] (warp 32m x 64n) ----
        {
            float acc[64];
#pragma unroll
            for (int i = 0; i < 64; ++i) acc[i] = 0.f;
            wgemm2<8, 4>(acc, sb + SM_A + warpM * P_D, (u32)D_LOF, P_D,
                              sb + SM_B + ng * 64 * P_D, P_D);
            // epilogue: O-layer partial row sums per n-group
            float op[4] = {0.f, 0.f, 0.f, 0.f};
            const int wN = ng * 64;
#pragma unroll
            for (int im = 0; im < 2; ++im)
#pragma unroll
            for (int jn = 0; jn < 8; ++jn) {
                const int idx = (im * 8 + jn) * 4;
                const int c = wN + 8 * jn + 2 * t;
                op[im*2+0] += tanh_f(acc[idx+0] + cf[CF_BD2 + c])     * cf[CF_WO + c]
                            + tanh_f(acc[idx+1] + cf[CF_BD2 + c + 1]) * cf[CF_WO + c + 1];
                op[im*2+1] += tanh_f(acc[idx+2] + cf[CF_BD2 + c])     * cf[CF_WO + c]
                            + tanh_f(acc[idx+3] + cf[CF_BD2 + c + 1]) * cf[CF_WO + c + 1];
            }
#pragma unroll
            for (int i = 0; i < 4; ++i) {
                op[i] += __shfl_xor_sync(0xffffffffu, op[i], 1);
                op[i] += __shfl_xor_sync(0xffffffffu, op[i], 2);
            }
            if (t == 0) {
#pragma unroll
                for (int im = 0; im < 2; ++im)
#pragma unroll
                for (int rh = 0; rh < 2; ++rh)
                    cf[CF_OP + ng * 128 + warpM + 16 * im + 8 * rh + g] = op[im*2+rh];
            }
        }
        __syncthreads();

        if (tid < 128) {
            const float v = cf[CF_OP + tid] + cf[CF_OP + 128 + tid]
                          + cf[CF_OP + 256 + tid] + cf[CF_OP + 384 + tid] + cf[CF_BO];
            float e;  asm("ex2.approx.f32 %0, %1;" : "=f"(e)  : "f"(-1.442695041f * v));
            float sg; asm("rcp.approx.f32 %0, %1;" : "=f"(sg) : "f"(1.0f + e));
            if (nb + tid < Nn) out[nb + tid] = sg;
        }
    }
}

// ---------------- launch ----------------
extern "C" void kernel_launch(void* const* d_in, const int* in_sizes, int n_in,
                              void* d_out, int out_size)
{
    // order: x, edge_index, edge_attr, W1, b1, We1, be1, We2, be2,
    //        Wd1, bd1, Wd2, bd2, Wo, bo
    const float* edge_attr = (const float*)d_in[2];
    const float* W1  = (const float*)d_in[3];
    const float* b1  = (const float*)d_in[4];
    const float* We1 = (const float*)d_in[5];
    const float* be1 = (const float*)d_in[6];
    const float* We2 = (const float*)d_in[7];
    const float* be2 = (const float*)d_in[8];
    const float* Wd1 = (const float*)d_in[9];
    const float* bd1 = (const float*)d_in[10];
    const float* Wd2 = (const float*)d_in[11];
    const float* bd2 = (const float*)d_in[12];
    const float* Wo  = (const float*)d_in[13];
    const float* bo  = (const float*)d_in[14];
    float* out = (float*)d_out;

    const int Nn = out_size;
    const int ntiles = (Nn + 127) / 128;

    prep_weights<<<292, 256>>>(W1, We1, Wd2);   // 74752 elements

    cudaFuncSetAttribute(gnn_mma_kernel,
                         cudaFuncAttributeMaxDynamicSharedMemorySize, SMEM_BYTES);
    int sms = 148;
    cudaDeviceGetAttribute(&sms, cudaDevAttrMultiProcessorCount, 0);
    const int grid = ntiles < sms ? ntiles : sms;

    gnn_mma_kernel<<<grid, 512, SMEM_BYTES>>>(
        edge_attr, b1, be1, We2, be2, Wd1, bd1, bd2, Wo, bo, out, Nn, ntiles);
}

// round 15
// speedup vs baseline: 1.8594x; 1.2819x over previous
#include <cuda_runtime.h>
#include <cuda_fp16.h>

typedef unsigned int u32;

// ---------------- pitches (bytes) ----------------
#define P_MS  48     /* msgs / W1t rows: K=16+8 pad  */
#define P_H   528    /* h plane / We1 rows: 256+8    */
#define P_D   272    /* d plane / Wd2 rows: 128+8    */

// ---------------- smem layout (bytes) ----------------
// Activation region 0..67584 (time-multiplexed):
//   msgs fp16 @0 (6144) -> h plane @0 (67584) -> d plane @0 (34816)
//   ZP floats @34816 (12288)   [written after E1 GEMM barrier]
//   OP floats @34816 (2048)    [aliases ZP, written in D2 epilogue]
//   raw edge_attr @59392 (8192)[written during D2 / consumed at tile start]
#define MSGS    0
#define ZPOFF   34816
#define RAWB    59392
// Resident weights (loaded once per block):
#define SM_W1   67584            /* 12288  */
#define SM_WE1  79872            /* 67584  */
#define SM_WD2  147456           /* 69632  */
#define SM_C    217088
// const region (float offsets from SM_C)
#define CF_B1   0
#define CF_BE1  256
#define CF_WE2  384
#define CF_BE2  1152
#define CF_WD1  1160
#define CF_BD1  1928
#define CF_BD2  2056
#define CF_WO   2312
#define CF_BO   2568
#define CF_TOT  2572
#define SMEM_BYTES (SM_C + CF_TOT*4)   /* 227,376 <= 232,448 */

// ---------------- pre-transposed single-plane fp16 weight images ------------
__device__ __align__(16) unsigned char g_W1t[12288];   // [256n][24k]
__device__ __align__(16) unsigned char g_We1t[67584];  // [128n][264k]
__device__ __align__(16) unsigned char g_Wd2t[69632];  // [256n][136k]

// ---------------- helpers ----------------
__device__ __forceinline__ u32 smem_u32(const void* p) {
    u32 a;
    asm("{ .reg .u64 t; cvta.to.shared.u64 t, %1; cvt.u32.u64 %0, t; }"
        : "=r"(a) : "l"(p));
    return a;
}
__device__ __forceinline__ void ldmx4(u32& r0, u32& r1, u32& r2, u32& r3, u32 addr) {
    asm volatile("ldmatrix.sync.aligned.m8n8.x4.shared.b16 {%0,%1,%2,%3}, [%4];"
                 : "=r"(r0), "=r"(r1), "=r"(r2), "=r"(r3) : "r"(addr));
}
__device__ __forceinline__ void mmah(float* c, u32 a0, u32 a1, u32 a2, u32 a3,
                                     u32 b0, u32 b1) {
    asm volatile("mma.sync.aligned.m16n8k16.row.col.f32.f16.f16.f32 "
                 "{%0,%1,%2,%3}, {%4,%5,%6,%7}, {%8,%9}, {%0,%1,%2,%3};"
                 : "+f"(c[0]), "+f"(c[1]), "+f"(c[2]), "+f"(c[3])
                 : "r"(a0), "r"(a1), "r"(a2), "r"(a3), "r"(b0), "r"(b1));
}
__device__ __forceinline__ float tanh_f(float x) {
    float e; asm("ex2.approx.f32 %0, %1;" : "=f"(e) : "f"(x * 2.885390082f));
    float r; asm("rcp.approx.f32 %0, %1;" : "=f"(r) : "f"(e + 1.0f));
    return fmaf(-2.0f, r, 1.0f);
}
__device__ __forceinline__ u32 pack_h(float x0, float x1) {
    __half h0 = __float2half_rn(x0), h1 = __float2half_rn(x1);
    return (u32)__half_as_ushort(h0) | ((u32)__half_as_ushort(h1) << 16);
}
__device__ __forceinline__ void cpa_g(u32 dst, const void* src, int ss) {
    asm volatile("cp.async.cg.shared.global [%0], [%1], 16, %2;"
                 :: "r"(dst), "l"(src), "r"(ss));
}
#define CP_COMMIT() asm volatile("cp.async.commit_group;" ::: "memory")
#define CP_WAIT(N)  asm volatile("cp.async.wait_group %0;" :: "n"(N) : "memory")

// ---------------- prep: transpose weights to fp16 images -------------------
__global__ void prep_weights(const float* __restrict__ W1,
                             const float* __restrict__ We1,
                             const float* __restrict__ Wd2)
{
    int idx = blockIdx.x * 256 + threadIdx.x;
    if (idx < 6144) {                              // W1t [256n][24k]
        int n = idx / 24, k = idx % 24;
        float v = (k < 16) ? W1[k * 256 + n] : 0.f;
        *(__half*)(g_W1t + n * P_MS + k * 2) = __float2half_rn(v);
        return;
    }
    idx -= 6144;
    if (idx < 33792) {                             // We1t [128n][264k]
        int n = idx / 264, kk = idx % 264;
        float v = (kk < 256) ? We1[kk * 128 + n] : 0.f;
        *(__half*)(g_We1t + n * P_H + kk * 2) = __float2half_rn(v);
        return;
    }
    idx -= 33792;
    if (idx < 34816) {                             // Wd2t [256n][136k]
        int n = idx / 136, kk = idx % 136;
        float v = (kk < 128) ? Wd2[kk * 256 + n] : 0.f;
        *(__half*)(g_Wd2t + n * P_D + kk * 2) = __float2half_rn(v);
    }
}

// ------ single-pass warp GEMM: A fp16 plane, B fp16 plane ------------------
template<int KSTEPS, int NPAIRS>
__device__ __forceinline__ void wgemm1(float* acc, u32 aBase, int aPitch,
                                       u32 bBase, int bPitch)
{
    const int lane = threadIdx.x & 31;
    const u32 aAddr = aBase + (u32)((lane & 15) * aPitch + ((lane >> 4) << 4));
    const int q = lane >> 3;
    const u32 bAddr = bBase + (u32)((((q >> 1) << 3) + (lane & 7)) * bPitch
                                    + ((q & 1) << 4));
#pragma unroll
    for (int ks = 0; ks < KSTEPS; ++ks) {
        u32 a0, a1, a2, a3, a4, a5, a6, a7;
        ldmx4(a0, a1, a2, a3, aAddr + ks * 32);
        ldmx4(a4, a5, a6, a7, aAddr + 16 * aPitch + ks * 32);
#pragma unroll
        for (int np = 0; np < NPAIRS; ++np) {
            u32 b0, b1, b2, b3;
            ldmx4(b0, b1, b2, b3, bAddr + np * 16 * bPitch + ks * 32);
            mmah(acc + (0 * 2 * NPAIRS + 2 * np + 0) * 4, a0, a1, a2, a3, b0, b1);
            mmah(acc + (0 * 2 * NPAIRS + 2 * np + 1) * 4, a0, a1, a2, a3, b2, b3);
            mmah(acc + (1 * 2 * NPAIRS + 2 * np + 0) * 4, a4, a5, a6, a7, b0, b1);
            mmah(acc + (1 * 2 * NPAIRS + 2 * np + 1) * 4, a4, a5, a6, a7, b2, b3);
        }
    }
}

// ---------------- main fused kernel (512 threads, 16 warps) ----------------
__global__ void __launch_bounds__(512, 1)
gnn_mma_kernel(const float* __restrict__ edge_attr,
               const float* __restrict__ b1,  const float* __restrict__ be1,
               const float* __restrict__ We2, const float* __restrict__ be2,
               const float* __restrict__ Wd1, const float* __restrict__ bd1,
               const float* __restrict__ bd2, const float* __restrict__ Wo,
               const float* __restrict__ bo,
               float* __restrict__ out, int Nn, int ntiles)
{
    extern __shared__ unsigned char smem[];
    float* cf  = (float*)(smem + SM_C);
    float* zpf = (float*)(smem + ZPOFF);      // ZP (and OP alias) partials
    const int tid = threadIdx.x;
    const int w = tid >> 5, lane = tid & 31;
    const int g = lane >> 2, t = lane & 3;
    const int warpM = (w & 3) * 32;           // m-group 0..3
    const int ng = w >> 2;                    // n-group 0..3
    const u32 sb = smem_u32(smem);

    // constants (strided loops cover full ranges at 512 threads)
    if (tid < 256) cf[CF_B1 + tid] = b1[tid];
    if (tid < 128) cf[CF_BE1 + tid] = be1[tid];
    for (int i = tid; i < 768; i += 512) cf[CF_WE2 + i] = We2[i];
    if (tid < 6)   cf[CF_BE2 + tid] = be2[tid];
    {
        int i = tid - 256;
        if (i >= 0 && i < 256) { cf[CF_BD2 + i] = bd2[i]; cf[CF_WO + i] = Wo[i]; }
    }
    if (tid >= 384 && tid < 512) cf[CF_BD1 + tid - 384] = bd1[tid - 384];
    for (int i = tid; i < 768; i += 512) cf[CF_WD1 + i] = Wd1[i];
    if (tid == 0)  cf[CF_BO] = bo[0];

    // resident weights: copy once (plain uint4 loads, ~150KB from L2)
    for (int i = tid; i < 768;  i += 512)
        *(uint4*)(smem + SM_W1  + i * 16) = *(const uint4*)(g_W1t  + i * 16);
    for (int i = tid; i < 4224; i += 512)
        *(uint4*)(smem + SM_WE1 + i * 16) = *(const uint4*)(g_We1t + i * 16);
    for (int i = tid; i < 4352; i += 512)
        *(uint4*)(smem + SM_WD2 + i * 16) = *(const uint4*)(g_Wd2t + i * 16);

    // prologue: prefetch first tile's raw edge_attr (512 x 16B = 8KB)
    {
        const int nb0 = blockIdx.x * 128;
        const int node = tid >> 2;
        cpa_g(sb + RAWB + tid * 16,
              edge_attr + (size_t)nb0 * 16 + tid * 4,
              (nb0 + node < Nn) ? 16 : 0);
        CP_COMMIT();
    }

    for (int tile = blockIdx.x; tile < ntiles; tile += gridDim.x) {
        const int nb = tile * 128;
        CP_WAIT(0);
        __syncthreads();                      // raw visible; prev-tile reads done

        // ---- transform raw -> msgs fp16 plane ----
        {
            const int node = tid >> 2;
            const float* rp = (const float*)(smem + RAWB) + node * 16 + t * 4;
            const float v0 = rp[0], v1 = rp[1], v2 = rp[2], v3 = rp[3];
            *(u32*)(smem + MSGS + node * P_MS + t * 8)     = pack_h(v0, v1);
            *(u32*)(smem + MSGS + node * P_MS + t * 8 + 4) = pack_h(v2, v3);
        }
        __syncthreads();

        // ---- L1: [128x16] @ [16x256] (warp 32m x 64n) ----
        float accL[64];
#pragma unroll
        for (int i = 0; i < 64; ++i) accL[i] = 0.f;
        wgemm1<1, 4>(accL, sb + MSGS + warpM * P_MS, P_MS,
                           sb + SM_W1 + ng * 64 * P_MS, P_MS);
        __syncthreads();                      // msgs reads done -> h can overwrite
        {
            const int wN = ng * 64;
#pragma unroll
            for (int im = 0; im < 2; ++im)
#pragma unroll
            for (int jn = 0; jn < 8; ++jn) {
                const int idx = (im * 8 + jn) * 4;
                const int c = wN + 8 * jn + 2 * t;
                const int r = warpM + 16 * im + g;
                *(u32*)(smem + r * P_H + c * 2) =
                    pack_h(tanh_f(accL[idx+0] + cf[CF_B1 + c]),
                           tanh_f(accL[idx+1] + cf[CF_B1 + c + 1]));
                *(u32*)(smem + (r + 8) * P_H + c * 2) =
                    pack_h(tanh_f(accL[idx+2] + cf[CF_B1 + c]),
                           tanh_f(accL[idx+3] + cf[CF_B1 + c + 1]));
            }
        }
        __syncthreads();                      // h plane visible

        // ---- E1: [128x256] @ [256x128] (warp 32m x 32n) ----
        float accE[32];
#pragma unroll
        for (int i = 0; i < 32; ++i) accE[i] = 0.f;
        wgemm1<16, 2>(accE, sb + warpM * P_H, P_H,
                            sb + SM_WE1 + ng * 32 * P_H, P_H);
        __syncthreads();                      // all h reads done -> ZP region safe
        {
            // E2 partials per n-group
            float zp[24];
#pragma unroll
            for (int i = 0; i < 24; ++i) zp[i] = 0.f;
            const int wN = ng * 32;
#pragma unroll
            for (int im = 0; im < 2; ++im)
#pragma unroll
            for (int jn = 0; jn < 4; ++jn) {
                const int idx = (im * 4 + jn) * 4;
                const int c = wN + 8 * jn + 2 * t;
                const float h0 = tanh_f(accE[idx+0] + cf[CF_BE1 + c]);
                const float h1 = tanh_f(accE[idx+1] + cf[CF_BE1 + c + 1]);
                const float h2 = tanh_f(accE[idx+2] + cf[CF_BE1 + c]);
                const float h3 = tanh_f(accE[idx+3] + cf[CF_BE1 + c + 1]);
                const float* w0 = &cf[CF_WE2 + c * 6];
                const float* w1 = &cf[CF_WE2 + (c + 1) * 6];
#pragma unroll
                for (int j = 0; j < 6; ++j) {
                    zp[(im*2+0)*6+j] += h0 * w0[j] + h1 * w1[j];
                    zp[(im*2+1)*6+j] += h2 * w0[j] + h3 * w1[j];
                }
            }
#pragma unroll
            for (int i = 0; i < 24; ++i) {
                zp[i] += __shfl_xor_sync(0xffffffffu, zp[i], 1);
                zp[i] += __shfl_xor_sync(0xffffffffu, zp[i], 2);
            }
            if (t == 0) {
#pragma unroll
                for (int im = 0; im < 2; ++im)
#pragma unroll
                for (int rh = 0; rh < 2; ++rh) {
                    const int r = warpM + 16 * im + 8 * rh + g;
#pragma unroll
                    for (int j = 0; j < 6; ++j)
                        zpf[ng * 768 + r * 6 + j] = zp[(im*2+rh)*6+j];
                }
            }
        }
        __syncthreads();                      // ZP visible

        // ---- prefetch next tile raw (h dead; region safe) ----
        {
            const int nb2 = (tile + gridDim.x) * 128;
            const int node = tid >> 2;
            cpa_g(sb + RAWB + tid * 16,
                  edge_attr + (size_t)nb2 * 16 + tid * 4,
                  (nb2 + node < Nn) ? 16 : 0);
            CP_COMMIT();
        }

        // ---- E2 finish + D1 -> d fp16 plane ----
        {
            const int r = tid >> 2;
            const int ih = t * 32;
            float z[6];
#pragma unroll
            for (int j = 0; j < 6; ++j)
                z[j] = tanh_f(zpf[r*6 + j]        + zpf[768 + r*6 + j]
                            + zpf[1536 + r*6 + j] + zpf[2304 + r*6 + j]
                            + cf[CF_BE2 + j]);
#pragma unroll 4
            for (int i = ih; i < ih + 32; i += 2) {
                float d0 = cf[CF_BD1 + i], d1 = cf[CF_BD1 + i + 1];
#pragma unroll
                for (int j = 0; j < 6; ++j) {
                    d0 = fmaf(z[j], cf[CF_WD1 + j * 128 + i],     d0);
                    d1 = fmaf(z[j], cf[CF_WD1 + j * 128 + i + 1], d1);
                }
                *(u32*)(smem + r * P_D + i * 2) = pack_h(tanh_f(d0), tanh_f(d1));
            }
        }
        __syncthreads();                      // d plane visible

        // ---- D2: [128x128] @ [128x256] (warp 32m x 64n) ----
        float accD[64];
#pragma unroll
        for (int i = 0; i < 64; ++i) accD[i] = 0.f;
        wgemm1<8, 4>(accD, sb + warpM * P_D, P_D,
                           sb + SM_WD2 + ng * 64 * P_D, P_D);
        {
            // O-layer partial row sums (OP region disjoint from d plane)
            float op[4] = {0.f, 0.f, 0.f, 0.f};
            const int wN = ng * 64;
#pragma unroll
            for (int im = 0; im < 2; ++im)
#pragma unroll
            for (int jn = 0; jn < 8; ++jn) {
                const int idx = (im * 8 + jn) * 4;
                const int c = wN + 8 * jn + 2 * t;
                op[im*2+0] += tanh_f(accD[idx+0] + cf[CF_BD2 + c])     * cf[CF_WO + c]
                            + tanh_f(accD[idx+1] + cf[CF_BD2 + c + 1]) * cf[CF_WO + c + 1];
                op[im*2+1] += tanh_f(accD[idx+2] + cf[CF_BD2 + c])     * cf[CF_WO + c]
                            + tanh_f(accD[idx+3] + cf[CF_BD2 + c + 1]) * cf[CF_WO + c + 1];
            }
#pragma unroll
            for (int i = 0; i < 4; ++i) {
                op[i] += __shfl_xor_sync(0xffffffffu, op[i], 1);
                op[i] += __shfl_xor_sync(0xffffffffu, op[i], 2);
            }
            if (t == 0) {
#pragma unroll
                for (int im = 0; im < 2; ++im)
#pragma unroll
                for (int rh = 0; rh < 2; ++rh)
                    zpf[ng * 128 + warpM + 16 * im + 8 * rh + g] = op[im*2+rh];
            }
        }
        __syncthreads();

        if (tid < 128) {
            const float v = zpf[tid] + zpf[128 + tid]
                          + zpf[256 + tid] + zpf[384 + tid] + cf[CF_BO];
            float e;  asm("ex2.approx.f32 %0, %1;" : "=f"(e)  : "f"(-1.442695041f * v));
            float sg; asm("rcp.approx.f32 %0, %1;" : "=f"(sg) : "f"(1.0f + e));
            if (nb + tid < Nn) out[nb + tid] = sg;
        }
    }
}

// ---------------- launch ----------------
extern "C" void kernel_launch(void* const* d_in, const int* in_sizes, int n_in,
                              void* d_out, int out_size)
{
    // order: x, edge_index, edge_attr, W1, b1, We1, be1, We2, be2,
    //        Wd1, bd1, Wd2, bd2, Wo, bo
    const float* edge_attr = (const float*)d_in[2];
    const float* W1  = (const float*)d_in[3];
    const float* b1  = (const float*)d_in[4];
    const float* We1 = (const float*)d_in[5];
    const float* be1 = (const float*)d_in[6];
    const float* We2 = (const float*)d_in[7];
    const float* be2 = (const float*)d_in[8];
    const float* Wd1 = (const float*)d_in[9];
    const float* bd1 = (const float*)d_in[10];
    const float* Wd2 = (const float*)d_in[11];
    const float* bd2 = (const float*)d_in[12];
    const float* Wo  = (const float*)d_in[13];
    const float* bo  = (const float*)d_in[14];
    float* out = (float*)d_out;

    const int Nn = out_size;
    const int ntiles = (Nn + 127) / 128;

    prep_weights<<<292, 256>>>(W1, We1, Wd2);   // 74752 elements

    cudaFuncSetAttribute(gnn_mma_kernel,
                         cudaFuncAttributeMaxDynamicSharedMemorySize, SMEM_BYTES);
    int sms = 148;
    cudaDeviceGetAttribute(&sms, cudaDevAttrMultiProcessorCount, 0);
    const int grid = ntiles < sms ? ntiles : sms;

    gnn_mma_kernel<<<grid, 512, SMEM_BYTES>>>(
        edge_attr, b1, be1, We2, be2, Wd1, bd1, bd2, Wo, bo, out, Nn, ntiles);
}

// round 16
// speedup vs baseline: 3.8771x; 2.0851x over previous
#include <cuda_runtime.h>
#include <cuda_fp16.h>

typedef unsigned int u32;

// ---------------- pitches (bytes) ----------------
#define P_MS  48     /* msgs / W1t / zplane / Wd1t rows: K pad to 24 halves */
#define P_H   528    /* h plane / We1 rows: 256+8    */
#define P_D   272    /* d plane / Wd2 rows: 128+8    */

// ---------------- smem layout (bytes) ----------------
// Activation region 0..67584 (time-multiplexed):
//   msgs fp16 @0 (6144) -> h plane @0 (67584) -> d plane @0 (34816)
//   ZP floats  @34816 (12288)  [written after E1 GEMM barrier]
//   OP floats  @34816 (2048)   [aliases ZP, written in D2 epilogue]
//   z fp16     @47104 (6144)   [written after ZP barrier]
//   raw attr   @59392 (8192)   [prefetched after E1; consumed at tile start]
#define MSGS    0
#define ZPOFF   34816
#define ZPLANE  47104
#define RAWB    59392
// Resident weights (loaded once per block):
#define SM_W1   67584            /* 12288  */
#define SM_WE1  79872            /* 67584  */
#define SM_WD2  147456           /* 69632  */
#define SM_WD1  217088           /* 6144   */
#define SM_C    223232
// const region (float offsets from SM_C)
#define CF_B1   0
#define CF_BE1  256
#define CF_WE2  384
#define CF_BE2  1152
#define CF_BD1  1160
#define CF_BD2  1288
#define CF_WO   1544
#define CF_BO   1800
#define CF_TOT  1804
#define SMEM_BYTES (SM_C + CF_TOT*4)   /* 230,448 <= 232,448 */

// ---------------- pre-transposed single-plane fp16 weight images ------------
__device__ __align__(16) unsigned char g_W1t[12288];   // [256n][24k]
__device__ __align__(16) unsigned char g_We1t[67584];  // [128n][264k]
__device__ __align__(16) unsigned char g_Wd2t[69632];  // [256n][136k]
__device__ __align__(16) unsigned char g_Wd1t[6144];   // [128n][24k] (K=6 pad)

// ---------------- helpers ----------------
__device__ __forceinline__ u32 smem_u32(const void* p) {
    u32 a;
    asm("{ .reg .u64 t; cvta.to.shared.u64 t, %1; cvt.u32.u64 %0, t; }"
        : "=r"(a) : "l"(p));
    return a;
}
__device__ __forceinline__ void ldmx4(u32& r0, u32& r1, u32& r2, u32& r3, u32 addr) {
    asm volatile("ldmatrix.sync.aligned.m8n8.x4.shared.b16 {%0,%1,%2,%3}, [%4];"
                 : "=r"(r0), "=r"(r1), "=r"(r2), "=r"(r3) : "r"(addr));
}
__device__ __forceinline__ void mmah(float* c, u32 a0, u32 a1, u32 a2, u32 a3,
                                     u32 b0, u32 b1) {
    asm volatile("mma.sync.aligned.m16n8k16.row.col.f32.f16.f16.f32 "
                 "{%0,%1,%2,%3}, {%4,%5,%6,%7}, {%8,%9}, {%0,%1,%2,%3};"
                 : "+f"(c[0]), "+f"(c[1]), "+f"(c[2]), "+f"(c[3])
                 : "r"(a0), "r"(a1), "r"(a2), "r"(a3), "r"(b0), "r"(b1));
}
// packed fp16 tanh: (lo,hi) floats -> half2 -> tanh.approx.f16x2 (1 MUFU / 2 tanh)
__device__ __forceinline__ u32 tanh_h2(float lo, float hi) {
    u32 p;
    asm("cvt.rn.f16x2.f32 %0, %1, %2;" : "=r"(p) : "f"(hi), "f"(lo));
    asm("tanh.approx.f16x2 %0, %0;" : "+r"(p));
    return p;
}
__device__ __forceinline__ float2 h22f2(u32 p) {
    __half2 h = *reinterpret_cast<__half2*>(&p);
    return __half22float2(h);
}
__device__ __forceinline__ u32 pack_h(float x0, float x1) {
    u32 p;
    asm("cvt.rn.f16x2.f32 %0, %1, %2;" : "=r"(p) : "f"(x1), "f"(x0));
    return p;
}
__device__ __forceinline__ void cpa_g(u32 dst, const void* src, int ss) {
    asm volatile("cp.async.cg.shared.global [%0], [%1], 16, %2;"
                 :: "r"(dst), "l"(src), "r"(ss));
}
#define CP_COMMIT() asm volatile("cp.async.commit_group;" ::: "memory")
#define CP_WAIT(N)  asm volatile("cp.async.wait_group %0;" :: "n"(N) : "memory")

// ---------------- prep: transpose weights to fp16 images -------------------
__global__ void prep_weights(const float* __restrict__ W1,
                             const float* __restrict__ We1,
                             const float* __restrict__ Wd2,
                             const float* __restrict__ Wd1)
{
    int idx = blockIdx.x * 256 + threadIdx.x;
    if (idx < 6144) {                              // W1t [256n][24k]
        int n = idx / 24, k = idx % 24;
        float v = (k < 16) ? W1[k * 256 + n] : 0.f;
        *(__half*)(g_W1t + n * P_MS + k * 2) = __float2half_rn(v);
        return;
    }
    idx -= 6144;
    if (idx < 33792) {                             // We1t [128n][264k]
        int n = idx / 264, kk = idx % 264;
        float v = (kk < 256) ? We1[kk * 128 + n] : 0.f;
        *(__half*)(g_We1t + n * P_H + kk * 2) = __float2half_rn(v);
        return;
    }
    idx -= 33792;
    if (idx < 34816) {                             // Wd2t [256n][136k]
        int n = idx / 136, kk = idx % 136;
        float v = (kk < 128) ? Wd2[kk * 256 + n] : 0.f;
        *(__half*)(g_Wd2t + n * P_D + kk * 2) = __float2half_rn(v);
        return;
    }
    idx -= 34816;
    if (idx < 3072) {                              // Wd1t [128n][24k] (K=6)
        int n = idx / 24, k = idx % 24;
        float v = (k < 6) ? Wd1[k * 128 + n] : 0.f;
        *(__half*)(g_Wd1t + n * P_MS + k * 2) = __float2half_rn(v);
    }
}

// ------ single-pass warp GEMM: A fp16 plane, B fp16 plane ------------------
template<int KSTEPS, int NPAIRS>
__device__ __forceinline__ void wgemm1(float* acc, u32 aBase, int aPitch,
                                       u32 bBase, int bPitch)
{
    const int lane = threadIdx.x & 31;
    const u32 aAddr = aBase + (u32)((lane & 15) * aPitch + ((lane >> 4) << 4));
    const int q = lane >> 3;
    const u32 bAddr = bBase + (u32)((((q >> 1) << 3) + (lane & 7)) * bPitch
                                    + ((q & 1) << 4));
#pragma unroll
    for (int ks = 0; ks < KSTEPS; ++ks) {
        u32 a0, a1, a2, a3, a4, a5, a6, a7;
        ldmx4(a0, a1, a2, a3, aAddr + ks * 32);
        ldmx4(a4, a5, a6, a7, aAddr + 16 * aPitch + ks * 32);
#pragma unroll
        for (int np = 0; np < NPAIRS; ++np) {
            u32 b0, b1, b2, b3;
            ldmx4(b0, b1, b2, b3, bAddr + np * 16 * bPitch + ks * 32);
            mmah(acc + (0 * 2 * NPAIRS + 2 * np + 0) * 4, a0, a1, a2, a3, b0, b1);
            mmah(acc + (0 * 2 * NPAIRS + 2 * np + 1) * 4, a0, a1, a2, a3, b2, b3);
            mmah(acc + (1 * 2 * NPAIRS + 2 * np + 0) * 4, a4, a5, a6, a7, b0, b1);
            mmah(acc + (1 * 2 * NPAIRS + 2 * np + 1) * 4, a4, a5, a6, a7, b2, b3);
        }
    }
}

// ---------------- main fused kernel (512 threads, 16 warps) ----------------
__global__ void __launch_bounds__(512, 1)
gnn_mma_kernel(const float* __restrict__ edge_attr,
               const float* __restrict__ b1,  const float* __restrict__ be1,
               const float* __restrict__ We2, const float* __restrict__ be2,
               const float* __restrict__ bd1, const float* __restrict__ bd2,
               const float* __restrict__ Wo,  const float* __restrict__ bo,
               float* __restrict__ out, int Nn, int ntiles)
{
    extern __shared__ unsigned char smem[];
    float* cf  = (float*)(smem + SM_C);
    float* zpf = (float*)(smem + ZPOFF);      // ZP (and OP alias) partials
    const int tid = threadIdx.x;
    const int w = tid >> 5, lane = tid & 31;
    const int g = lane >> 2, t = lane & 3;
    const int warpM = (w & 3) * 32;           // m-group 0..3
    const int ng = w >> 2;                    // n-group 0..3
    const u32 sb = smem_u32(smem);

    // constants
    if (tid < 256) cf[CF_B1 + tid] = b1[tid];
    if (tid < 128) cf[CF_BE1 + tid] = be1[tid];
    for (int i = tid; i < 768; i += 512) cf[CF_WE2 + i] = We2[i];
    if (tid < 6)   cf[CF_BE2 + tid] = be2[tid];
    if (tid >= 256 && tid < 384) cf[CF_BD1 + tid - 256] = bd1[tid - 256];
    if (tid < 256) { cf[CF_BD2 + tid] = bd2[tid]; cf[CF_WO + tid] = Wo[tid]; }
    if (tid == 0)  cf[CF_BO] = bo[0];

    // resident weights (once per block, ~156KB from L2)
    for (int i = tid; i < 768;  i += 512)
        *(uint4*)(smem + SM_W1  + i * 16) = *(const uint4*)(g_W1t  + i * 16);
    for (int i = tid; i < 4224; i += 512)
        *(uint4*)(smem + SM_WE1 + i * 16) = *(const uint4*)(g_We1t + i * 16);
    for (int i = tid; i < 4352; i += 512)
        *(uint4*)(smem + SM_WD2 + i * 16) = *(const uint4*)(g_Wd2t + i * 16);
    for (int i = tid; i < 384;  i += 512)
        *(uint4*)(smem + SM_WD1 + i * 16) = *(const uint4*)(g_Wd1t + i * 16);

    // prologue: prefetch first tile's raw edge_attr (8KB)
    {
        const int nb0 = blockIdx.x * 128;
        const int node = tid >> 2;
        cpa_g(sb + RAWB + tid * 16,
              edge_attr + (size_t)nb0 * 16 + tid * 4,
              (nb0 + node < Nn) ? 16 : 0);
        CP_COMMIT();
    }

    for (int tile = blockIdx.x; tile < ntiles; tile += gridDim.x) {
        const int nb = tile * 128;
        CP_WAIT(0);
        __syncthreads();                      // raw visible; prev-tile reads done

        // ---- raw -> msgs fp16 plane ----
        {
            const int node = tid >> 2;
            const float* rp = (const float*)(smem + RAWB) + node * 16 + t * 4;
            const float v0 = rp[0], v1 = rp[1], v2 = rp[2], v3 = rp[3];
            *(u32*)(smem + MSGS + node * P_MS + t * 8)     = pack_h(v0, v1);
            *(u32*)(smem + MSGS + node * P_MS + t * 8 + 4) = pack_h(v2, v3);
        }
        __syncthreads();

        // ---- L1: [128x16] @ [16x256] (warp 32m x 64n) ----
        float accL[64];
#pragma unroll
        for (int i = 0; i < 64; ++i) accL[i] = 0.f;
        wgemm1<1, 4>(accL, sb + MSGS + warpM * P_MS, P_MS,
                           sb + SM_W1 + ng * 64 * P_MS, P_MS);
        __syncthreads();                      // msgs reads done
        {
            const int wN = ng * 64;
#pragma unroll
            for (int im = 0; im < 2; ++im)
#pragma unroll
            for (int jn = 0; jn < 8; ++jn) {
                const int idx = (im * 8 + jn) * 4;
                const int c = wN + 8 * jn + 2 * t;
                const int r = warpM + 16 * im + g;
                const float bb0 = cf[CF_B1 + c], bb1 = cf[CF_B1 + c + 1];
                *(u32*)(smem + r * P_H + c * 2) =
                    tanh_h2(accL[idx+0] + bb0, accL[idx+1] + bb1);
                *(u32*)(smem + (r + 8) * P_H + c * 2) =
                    tanh_h2(accL[idx+2] + bb0, accL[idx+3] + bb1);
            }
        }
        __syncthreads();                      // h plane visible

        // ---- E1: [128x256] @ [256x128] (warp 32m x 32n) ----
        float accE[32];
#pragma unroll
        for (int i = 0; i < 32; ++i) accE[i] = 0.f;
        wgemm1<16, 2>(accE, sb + warpM * P_H, P_H,
                            sb + SM_WE1 + ng * 32 * P_H, P_H);
        __syncthreads();                      // h reads done -> ZP region safe
        {
            // tanh (f16x2) -> E2 partials per n-group
            float zp[24];
#pragma unroll
            for (int i = 0; i < 24; ++i) zp[i] = 0.f;
            const int wN = ng * 32;
#pragma unroll
            for (int im = 0; im < 2; ++im)
#pragma unroll
            for (int jn = 0; jn < 4; ++jn) {
                const int idx = (im * 4 + jn) * 4;
                const int c = wN + 8 * jn + 2 * t;
                const float bb0 = cf[CF_BE1 + c], bb1 = cf[CF_BE1 + c + 1];
                const float2 f01 = h22f2(tanh_h2(accE[idx+0] + bb0, accE[idx+1] + bb1));
                const float2 f23 = h22f2(tanh_h2(accE[idx+2] + bb0, accE[idx+3] + bb1));
                const float* w0 = &cf[CF_WE2 + c * 6];
                const float* w1 = &cf[CF_WE2 + (c + 1) * 6];
#pragma unroll
                for (int j = 0; j < 6; ++j) {
                    zp[(im*2+0)*6+j] += f01.x * w0[j] + f01.y * w1[j];
                    zp[(im*2+1)*6+j] += f23.x * w0[j] + f23.y * w1[j];
                }
            }
#pragma unroll
            for (int i = 0; i < 24; ++i) {
                zp[i] += __shfl_xor_sync(0xffffffffu, zp[i], 1);
                zp[i] += __shfl_xor_sync(0xffffffffu, zp[i], 2);
            }
            if (t == 0) {
#pragma unroll
                for (int im = 0; im < 2; ++im)
#pragma unroll
                for (int rh = 0; rh < 2; ++rh) {
                    const int r = warpM + 16 * im + 8 * rh + g;
#pragma unroll
                    for (int j = 0; j < 6; ++j)
                        zpf[ng * 768 + r * 6 + j] = zp[(im*2+rh)*6+j];
                }
            }
        }
        __syncthreads();                      // ZP visible; h dead

        // prefetch next tile raw (h region dead)
        {
            const int nb2 = (tile + gridDim.x) * 128;
            const int node = tid >> 2;
            cpa_g(sb + RAWB + tid * 16,
                  edge_attr + (size_t)nb2 * 16 + tid * 4,
                  (nb2 + node < Nn) ? 16 : 0);
            CP_COMMIT();
        }

        // ---- E2 finish: z -> fp16 K-padded plane (threads 0-127) ----
        if (tid < 128) {
            const int r = tid;
            float s[6];
#pragma unroll
            for (int j = 0; j < 6; ++j)
                s[j] = zpf[r*6 + j]        + zpf[768 + r*6 + j]
                     + zpf[1536 + r*6 + j] + zpf[2304 + r*6 + j]
                     + cf[CF_BE2 + j];
            u32* zrow = (u32*)(smem + ZPLANE + r * P_MS);
            zrow[0] = tanh_h2(s[0], s[1]);
            zrow[1] = tanh_h2(s[2], s[3]);
            zrow[2] = tanh_h2(s[4], s[5]);
            zrow[3] = 0u; zrow[4] = 0u; zrow[5] = 0u; zrow[6] = 0u; zrow[7] = 0u;
        }
        __syncthreads();                      // z plane visible

        // ---- D1 via MMA: [128x6(pad16)] @ [6x128] (warp 32m x 32n) ----
        float accD1[32];
#pragma unroll
        for (int i = 0; i < 32; ++i) accD1[i] = 0.f;
        wgemm1<1, 2>(accD1, sb + ZPLANE + warpM * P_MS, P_MS,
                            sb + SM_WD1 + ng * 32 * P_MS, P_MS);
        {
            const int wN = ng * 32;
#pragma unroll
            for (int im = 0; im < 2; ++im)
#pragma unroll
            for (int jn = 0; jn < 4; ++jn) {
                const int idx = (im * 4 + jn) * 4;
                const int c = wN + 8 * jn + 2 * t;
                const int r = warpM + 16 * im + g;
                const float bb0 = cf[CF_BD1 + c], bb1 = cf[CF_BD1 + c + 1];
                *(u32*)(smem + r * P_D + c * 2) =
                    tanh_h2(accD1[idx+0] + bb0, accD1[idx+1] + bb1);
                *(u32*)(smem + (r + 8) * P_D + c * 2) =
                    tanh_h2(accD1[idx+2] + bb0, accD1[idx+3] + bb1);
            }
        }
        __syncthreads();                      // d plane visible

        // ---- D2: [128x128] @ [128x256] (warp 32m x 64n) ----
        float accD[64];
#pragma unroll
        for (int i = 0; i < 64; ++i) accD[i] = 0.f;
        wgemm1<8, 4>(accD, sb + warpM * P_D, P_D,
                           sb + SM_WD2 + ng * 64 * P_D, P_D);
        {
            // O-layer partial row sums (OP region disjoint from d plane)
            float op[4] = {0.f, 0.f, 0.f, 0.f};
            const int wN = ng * 64;
#pragma unroll
            for (int im = 0; im < 2; ++im)
#pragma unroll
            for (int jn = 0; jn < 8; ++jn) {
                const int idx = (im * 8 + jn) * 4;
                const int c = wN + 8 * jn + 2 * t;
                const float bb0 = cf[CF_BD2 + c], bb1 = cf[CF_BD2 + c + 1];
                const float w0 = cf[CF_WO + c],  w1 = cf[CF_WO + c + 1];
                const float2 f01 = h22f2(tanh_h2(accD[idx+0] + bb0, accD[idx+1] + bb1));
                const float2 f23 = h22f2(tanh_h2(accD[idx+2] + bb0, accD[idx+3] + bb1));
                op[im*2+0] += f01.x * w0 + f01.y * w1;
                op[im*2+1] += f23.x * w0 + f23.y * w1;
            }
#pragma unroll
            for (int i = 0; i < 4; ++i) {
                op[i] += __shfl_xor_sync(0xffffffffu, op[i], 1);
                op[i] += __shfl_xor_sync(0xffffffffu, op[i], 2);
            }
            if (t == 0) {
#pragma unroll
                for (int im = 0; im < 2; ++im)
#pragma unroll
                for (int rh = 0; rh < 2; ++rh)
                    zpf[ng * 128 + warpM + 16 * im + 8 * rh + g] = op[im*2+rh];
            }
        }
        __syncthreads();

        if (tid < 128) {
            const float v = zpf[tid] + zpf[128 + tid]
                          + zpf[256 + tid] + zpf[384 + tid] + cf[CF_BO];
            float e;  asm("ex2.approx.f32 %0, %1;" : "=f"(e)  : "f"(-1.442695041f * v));
            float sg; asm("rcp.approx.f32 %0, %1;" : "=f"(sg) : "f"(1.0f + e));
            if (nb + tid < Nn) out[nb + tid] = sg;
        }
    }
}

// ---------------- launch ----------------
extern "C" void kernel_launch(void* const* d_in, const int* in_sizes, int n_in,
                              void* d_out, int out_size)
{
    // order: x, edge_index, edge_attr, W1, b1, We1, be1, We2, be2,
    //        Wd1, bd1, Wd2, bd2, Wo, bo
    const float* edge_attr = (const float*)d_in[2];
    const float* W1  = (const float*)d_in[3];
    const float* b1  = (const float*)d_in[4];
    const float* We1 = (const float*)d_in[5];
    const float* be1 = (const float*)d_in[6];
    const float* We2 = (const float*)d_in[7];
    const float* be2 = (const float*)d_in[8];
    const float* Wd1 = (const float*)d_in[9];
    const float* bd1 = (const float*)d_in[10];
    const float* Wd2 = (const float*)d_in[11];
    const float* bd2 = (const float*)d_in[12];
    const float* Wo  = (const float*)d_in[13];
    const float* bo  = (const float*)d_in[14];
    float* out = (float*)d_out;

    const int Nn = out_size;
    const int ntiles = (Nn + 127) / 128;

    prep_weights<<<304, 256>>>(W1, We1, Wd2, Wd1);   // 77824 elements

    cudaFuncSetAttribute(gnn_mma_kernel,
                         cudaFuncAttributeMaxDynamicSharedMemorySize, SMEM_BYTES);
    int sms = 148;
    cudaDeviceGetAttribute(&sms, cudaDevAttrMultiProcessorCount, 0);
    const int grid = ntiles < sms ? ntiles : sms;

    gnn_mma_kernel<<<grid, 512, SMEM_BYTES>>>(
        edge_attr, b1, be1, We2, be2, bd1, bd2, Wo, bo, out, Nn, ntiles);
}

// round 17
// speedup vs baseline: 4.0085x; 1.0339x over previous
#include <cuda_runtime.h>
#include <cuda_fp16.h>

typedef unsigned int u32;

// ---------------- pitches (bytes) ----------------
#define P_MS  48     /* msgs / W1t / zplane / Wd1t rows: K pad to 24 halves */
#define P_H   528    /* h plane / We1 rows: 256+8    */
#define P_D   272    /* d plane / Wd2 rows: 128+8    */

// ---------------- smem layout (bytes) ----------------
// Two per-half activation regions (64 rows each), base A = hw*HREG:
//   h plane  @A+0      (33792)  [rows 0..63]
//   d plane  @A+0      (17408)  [after h dead]
//   ZP/OP    @A+17408  (6144)   [E1 partials; OP aliases]
//   zplane   @A+23552  (3072)
//   raw attr @A+26624  (4096)
//   msgs     @A+30720  (3072)
#define HREG    33792
#define ZP_B    17408
#define ZPL_B   23552
#define RAW_B   26624
#define MSG_B   30720
// Resident weights (shared, loaded once per block):
#define SM_W1   67584            /* 12288  */
#define SM_WE1  79872            /* 67584  */
#define SM_WD2  147456           /* 69632  */
#define SM_WD1  217088           /* 6144   */
#define SM_C    223232
// const region (float offsets from SM_C)
#define CF_B1   0
#define CF_BE1  256
#define CF_WE2  384
#define CF_BE2  1152
#define CF_BD1  1160
#define CF_BD2  1288
#define CF_WO   1544
#define CF_BO   1800
#define CF_TOT  1804
#define SMEM_BYTES (SM_C + CF_TOT*4)   /* 230,448 <= 232,448 */

// ---------------- pre-transposed single-plane fp16 weight images ------------
__device__ __align__(16) unsigned char g_W1t[12288];   // [256n][24k]
__device__ __align__(16) unsigned char g_We1t[67584];  // [128n][264k]
__device__ __align__(16) unsigned char g_Wd2t[69632];  // [256n][136k]
__device__ __align__(16) unsigned char g_Wd1t[6144];   // [128n][24k] (K=6 pad)

// ---------------- helpers ----------------
__device__ __forceinline__ u32 smem_u32(const void* p) {
    u32 a;
    asm("{ .reg .u64 t; cvta.to.shared.u64 t, %1; cvt.u32.u64 %0, t; }"
        : "=r"(a) : "l"(p));
    return a;
}
__device__ __forceinline__ void hbar(int id) {
    asm volatile("bar.sync %0, 256;" :: "r"(id) : "memory");
}
__device__ __forceinline__ void ldmx4(u32& r0, u32& r1, u32& r2, u32& r3, u32 addr) {
    asm volatile("ldmatrix.sync.aligned.m8n8.x4.shared.b16 {%0,%1,%2,%3}, [%4];"
                 : "=r"(r0), "=r"(r1), "=r"(r2), "=r"(r3) : "r"(addr));
}
__device__ __forceinline__ void mmah(float* c, u32 a0, u32 a1, u32 a2, u32 a3,
                                     u32 b0, u32 b1) {
    asm volatile("mma.sync.aligned.m16n8k16.row.col.f32.f16.f16.f32 "
                 "{%0,%1,%2,%3}, {%4,%5,%6,%7}, {%8,%9}, {%0,%1,%2,%3};"
                 : "+f"(c[0]), "+f"(c[1]), "+f"(c[2]), "+f"(c[3])
                 : "r"(a0), "r"(a1), "r"(a2), "r"(a3), "r"(b0), "r"(b1));
}
// packed fp16 tanh: 1 MUFU per 2 tanh
__device__ __forceinline__ u32 tanh_h2(float lo, float hi) {
    u32 p;
    asm("cvt.rn.f16x2.f32 %0, %1, %2;" : "=r"(p) : "f"(hi), "f"(lo));
    asm("tanh.approx.f16x2 %0, %0;" : "+r"(p));
    return p;
}
__device__ __forceinline__ float2 h22f2(u32 p) {
    __half2 h = *reinterpret_cast<__half2*>(&p);
    return __half22float2(h);
}
__device__ __forceinline__ u32 pack_h(float x0, float x1) {
    u32 p;
    asm("cvt.rn.f16x2.f32 %0, %1, %2;" : "=r"(p) : "f"(x1), "f"(x0));
    return p;
}
__device__ __forceinline__ void cpa_g(u32 dst, const void* src, int ss) {
    asm volatile("cp.async.cg.shared.global [%0], [%1], 16, %2;"
                 :: "r"(dst), "l"(src), "r"(ss));
}
#define CP_COMMIT() asm volatile("cp.async.commit_group;" ::: "memory")
#define CP_WAIT(N)  asm volatile("cp.async.wait_group %0;" :: "n"(N) : "memory")

// ---------------- prep: transpose weights to fp16 images -------------------
__global__ void prep_weights(const float* __restrict__ W1,
                             const float* __restrict__ We1,
                             const float* __restrict__ Wd2,
                             const float* __restrict__ Wd1)
{
    int idx = blockIdx.x * 256 + threadIdx.x;
    if (idx < 6144) {                              // W1t [256n][24k]
        int n = idx / 24, k = idx % 24;
        float v = (k < 16) ? W1[k * 256 + n] : 0.f;
        *(__half*)(g_W1t + n * P_MS + k * 2) = __float2half_rn(v);
        return;
    }
    idx -= 6144;
    if (idx < 33792) {                             // We1t [128n][264k]
        int n = idx / 264, kk = idx % 264;
        float v = (kk < 256) ? We1[kk * 128 + n] : 0.f;
        *(__half*)(g_We1t + n * P_H + kk * 2) = __float2half_rn(v);
        return;
    }
    idx -= 33792;
    if (idx < 34816) {                             // Wd2t [256n][136k]
        int n = idx / 136, kk = idx % 136;
        float v = (kk < 128) ? Wd2[kk * 256 + n] : 0.f;
        *(__half*)(g_Wd2t + n * P_D + kk * 2) = __float2half_rn(v);
        return;
    }
    idx -= 34816;
    if (idx < 3072) {                              // Wd1t [128n][24k] (K=6)
        int n = idx / 24, k = idx % 24;
        float v = (k < 6) ? Wd1[k * 128 + n] : 0.f;
        *(__half*)(g_Wd1t + n * P_MS + k * 2) = __float2half_rn(v);
    }
}

// ------ single-pass warp GEMM: A fp16 plane, B fp16 plane ------------------
template<int KSTEPS, int NPAIRS>
__device__ __forceinline__ void wgemm1(float* acc, u32 aBase, int aPitch,
                                       u32 bBase, int bPitch)
{
    const int lane = threadIdx.x & 31;
    const u32 aAddr = aBase + (u32)((lane & 15) * aPitch + ((lane >> 4) << 4));
    const int q = lane >> 3;
    const u32 bAddr = bBase + (u32)((((q >> 1) << 3) + (lane & 7)) * bPitch
                                    + ((q & 1) << 4));
#pragma unroll
    for (int ks = 0; ks < KSTEPS; ++ks) {
        u32 a0, a1, a2, a3, a4, a5, a6, a7;
        ldmx4(a0, a1, a2, a3, aAddr + ks * 32);
        ldmx4(a4, a5, a6, a7, aAddr + 16 * aPitch + ks * 32);
#pragma unroll
        for (int np = 0; np < NPAIRS; ++np) {
            u32 b0, b1, b2, b3;
            ldmx4(b0, b1, b2, b3, bAddr + np * 16 * bPitch + ks * 32);
            mmah(acc + (0 * 2 * NPAIRS + 2 * np + 0) * 4, a0, a1, a2, a3, b0, b1);
            mmah(acc + (0 * 2 * NPAIRS + 2 * np + 1) * 4, a0, a1, a2, a3, b2, b3);
            mmah(acc + (1 * 2 * NPAIRS + 2 * np + 0) * 4, a4, a5, a6, a7, b0, b1);
            mmah(acc + (1 * 2 * NPAIRS + 2 * np + 1) * 4, a4, a5, a6, a7, b2, b3);
        }
    }
}

// ------- main fused kernel: 512 threads = two independent 64-row halves -----
__global__ void __launch_bounds__(512, 1)
gnn_mma_kernel(const float* __restrict__ edge_attr,
               const float* __restrict__ b1,  const float* __restrict__ be1,
               const float* __restrict__ We2, const float* __restrict__ be2,
               const float* __restrict__ bd1, const float* __restrict__ bd2,
               const float* __restrict__ Wo,  const float* __restrict__ bo,
               float* __restrict__ out, int Nn, int ntiles)
{
    extern __shared__ unsigned char smem[];
    float* cf = (float*)(smem + SM_C);
    const int tid  = threadIdx.x;
    const int hw   = tid >> 8;            // half 0/1
    const int htid = tid & 255;
    const int w8   = htid >> 5;           // warp-in-half 0..7
    const int lane = tid & 31;
    const int g = lane >> 2, t = lane & 3;
    const int warpM = (w8 & 1) * 32;      // 2 m-groups of 32 rows
    const int ng    = w8 >> 1;            // 4 n-groups
    const int barid = hw + 1;             // named barrier per half
    const u32 A  = (u32)hw * HREG;        // per-half activation base (bytes)
    const u32 sb = smem_u32(smem);
    float* zh = (float*)(smem + A + ZP_B);   // per-half ZP/OP partials

    // constants (shared)
    if (tid < 256) cf[CF_B1 + tid] = b1[tid];
    if (tid < 128) cf[CF_BE1 + tid] = be1[tid];
    for (int i = tid; i < 768; i += 512) cf[CF_WE2 + i] = We2[i];
    if (tid < 6)   cf[CF_BE2 + tid] = be2[tid];
    if (tid >= 256 && tid < 384) cf[CF_BD1 + tid - 256] = bd1[tid - 256];
    if (tid < 256) { cf[CF_BD2 + tid] = bd2[tid]; cf[CF_WO + tid] = Wo[tid]; }
    if (tid == 0)  cf[CF_BO] = bo[0];

    // resident weights (once per block)
    for (int i = tid; i < 768;  i += 512)
        *(uint4*)(smem + SM_W1  + i * 16) = *(const uint4*)(g_W1t  + i * 16);
    for (int i = tid; i < 4224; i += 512)
        *(uint4*)(smem + SM_WE1 + i * 16) = *(const uint4*)(g_We1t + i * 16);
    for (int i = tid; i < 4352; i += 512)
        *(uint4*)(smem + SM_WD2 + i * 16) = *(const uint4*)(g_Wd2t + i * 16);
    for (int i = tid; i < 384;  i += 512)
        *(uint4*)(smem + SM_WD1 + i * 16) = *(const uint4*)(g_Wd1t + i * 16);

    // prologue: prefetch this half's first raw sub-tile (64 nodes x 64B)
    {
        const int nb0 = blockIdx.x * 128 + hw * 64;
        const int node = htid >> 2;
        cpa_g(sb + A + RAW_B + htid * 16,
              edge_attr + (size_t)nb0 * 16 + htid * 4,
              (nb0 + node < Nn) ? 16 : 0);
        CP_COMMIT();
    }
    __syncthreads();                      // weights + consts visible to all

    for (int tile = blockIdx.x; tile < ntiles; tile += gridDim.x) {
        const int nb = tile * 128 + hw * 64;
        CP_WAIT(0);
        hbar(barid);                      // raw visible; prev-tile reads done

        // ---- raw -> msgs fp16 plane (64 rows) ----
        {
            const int node = htid >> 2;
            const float* rp = (const float*)(smem + A + RAW_B) + node * 16 + t * 4;
            const float v0 = rp[0], v1 = rp[1], v2 = rp[2], v3 = rp[3];
            *(u32*)(smem + A + MSG_B + node * P_MS + t * 8)     = pack_h(v0, v1);
            *(u32*)(smem + A + MSG_B + node * P_MS + t * 8 + 4) = pack_h(v2, v3);
        }
        hbar(barid);

        // ---- L1: [64x16] @ [16x256] (warp 32m x 64n) ----
        float accL[64];
#pragma unroll
        for (int i = 0; i < 64; ++i) accL[i] = 0.f;
        wgemm1<1, 4>(accL, sb + A + MSG_B + warpM * P_MS, P_MS,
                           sb + SM_W1 + ng * 64 * P_MS, P_MS);
        hbar(barid);                      // msgs reads done -> h may overwrite
        {
            const int wN = ng * 64;
#pragma unroll
            for (int im = 0; im < 2; ++im)
#pragma unroll
            for (int jn = 0; jn < 8; ++jn) {
                const int idx = (im * 8 + jn) * 4;
                const int c = wN + 8 * jn + 2 * t;
                const int r = warpM + 16 * im + g;
                const float bb0 = cf[CF_B1 + c], bb1 = cf[CF_B1 + c + 1];
                *(u32*)(smem + A + r * P_H + c * 2) =
                    tanh_h2(accL[idx+0] + bb0, accL[idx+1] + bb1);
                *(u32*)(smem + A + (r + 8) * P_H + c * 2) =
                    tanh_h2(accL[idx+2] + bb0, accL[idx+3] + bb1);
            }
        }
        hbar(barid);                      // h plane visible

        // ---- E1: [64x256] @ [256x128] (warp 32m x 32n) ----
        float accE[32];
#pragma unroll
        for (int i = 0; i < 32; ++i) accE[i] = 0.f;
        wgemm1<16, 2>(accE, sb + A + warpM * P_H, P_H,
                            sb + SM_WE1 + ng * 32 * P_H, P_H);
        hbar(barid);                      // h reads done -> ZP region safe
        {
            float zp[24];
#pragma unroll
            for (int i = 0; i < 24; ++i) zp[i] = 0.f;
            const int wN = ng * 32;
#pragma unroll
            for (int im = 0; im < 2; ++im)
#pragma unroll
            for (int jn = 0; jn < 4; ++jn) {
                const int idx = (im * 4 + jn) * 4;
                const int c = wN + 8 * jn + 2 * t;
                const float bb0 = cf[CF_BE1 + c], bb1 = cf[CF_BE1 + c + 1];
                const float2 f01 = h22f2(tanh_h2(accE[idx+0] + bb0, accE[idx+1] + bb1));
                const float2 f23 = h22f2(tanh_h2(accE[idx+2] + bb0, accE[idx+3] + bb1));
                const float* w0 = &cf[CF_WE2 + c * 6];
                const float* w1 = &cf[CF_WE2 + (c + 1) * 6];
#pragma unroll
                for (int j = 0; j < 6; ++j) {
                    zp[(im*2+0)*6+j] += f01.x * w0[j] + f01.y * w1[j];
                    zp[(im*2+1)*6+j] += f23.x * w0[j] + f23.y * w1[j];
                }
            }
#pragma unroll
            for (int i = 0; i < 24; ++i) {
                zp[i] += __shfl_xor_sync(0xffffffffu, zp[i], 1);
                zp[i] += __shfl_xor_sync(0xffffffffu, zp[i], 2);
            }
            if (t == 0) {
#pragma unroll
                for (int im = 0; im < 2; ++im)
#pragma unroll
                for (int rh = 0; rh < 2; ++rh) {
                    const int r = warpM + 16 * im + 8 * rh + g;   // 0..63
#pragma unroll
                    for (int j = 0; j < 6; ++j)
                        zh[ng * 384 + r * 6 + j] = zp[(im*2+rh)*6+j];
                }
            }
        }
        hbar(barid);                      // ZP visible; h dead

        // prefetch next tile raw (h region dead)
        {
            const int nb2 = (tile + gridDim.x) * 128 + hw * 64;
            const int node = htid >> 2;
            cpa_g(sb + A + RAW_B + htid * 16,
                  edge_attr + (size_t)nb2 * 16 + htid * 4,
                  (nb2 + node < Nn) ? 16 : 0);
            CP_COMMIT();
        }

        // ---- E2 finish: z -> fp16 K-padded plane (htid < 64) ----
        if (htid < 64) {
            const int r = htid;
            float s[6];
#pragma unroll
            for (int j = 0; j < 6; ++j)
                s[j] = zh[r*6 + j]        + zh[384 + r*6 + j]
                     + zh[768 + r*6 + j]  + zh[1152 + r*6 + j]
                     + cf[CF_BE2 + j];
            u32* zrow = (u32*)(smem + A + ZPL_B + r * P_MS);
            zrow[0] = tanh_h2(s[0], s[1]);
            zrow[1] = tanh_h2(s[2], s[3]);
            zrow[2] = tanh_h2(s[4], s[5]);
            zrow[3] = 0u; zrow[4] = 0u; zrow[5] = 0u; zrow[6] = 0u; zrow[7] = 0u;
        }
        hbar(barid);                      // z plane visible

        // ---- D1 via MMA: [64x6(pad16)] @ [6x128] (warp 32m x 32n) ----
        float accD1[32];
#pragma unroll
        for (int i = 0; i < 32; ++i) accD1[i] = 0.f;
        wgemm1<1, 2>(accD1, sb + A + ZPL_B + warpM * P_MS, P_MS,
                            sb + SM_WD1 + ng * 32 * P_MS, P_MS);
        {
            const int wN = ng * 32;
#pragma unroll
            for (int im = 0; im < 2; ++im)
#pragma unroll
            for (int jn = 0; jn < 4; ++jn) {
                const int idx = (im * 4 + jn) * 4;
                const int c = wN + 8 * jn + 2 * t;
                const int r = warpM + 16 * im + g;
                const float bb0 = cf[CF_BD1 + c], bb1 = cf[CF_BD1 + c + 1];
                *(u32*)(smem + A + r * P_D + c * 2) =
                    tanh_h2(accD1[idx+0] + bb0, accD1[idx+1] + bb1);
                *(u32*)(smem + A + (r + 8) * P_D + c * 2) =
                    tanh_h2(accD1[idx+2] + bb0, accD1[idx+3] + bb1);
            }
        }
        hbar(barid);                      // d plane visible

        // ---- D2: [64x128] @ [128x256] (warp 32m x 64n) ----
        float accD[64];
#pragma unroll
        for (int i = 0; i < 64; ++i) accD[i] = 0.f;
        wgemm1<8, 4>(accD, sb + A + warpM * P_D, P_D,
                           sb + SM_WD2 + ng * 64 * P_D, P_D);
        {
            float op[4] = {0.f, 0.f, 0.f, 0.f};
            const int wN = ng * 64;
#pragma unroll
            for (int im = 0; im < 2; ++im)
#pragma unroll
            for (int jn = 0; jn < 8; ++jn) {
                const int idx = (im * 8 + jn) * 4;
                const int c = wN + 8 * jn + 2 * t;
                const float bb0 = cf[CF_BD2 + c], bb1 = cf[CF_BD2 + c + 1];
                const float w0 = cf[CF_WO + c],  w1 = cf[CF_WO + c + 1];
                const float2 f01 = h22f2(tanh_h2(accD[idx+0] + bb0, accD[idx+1] + bb1));
                const float2 f23 = h22f2(tanh_h2(accD[idx+2] + bb0, accD[idx+3] + bb1));
                op[im*2+0] += f01.x * w0 + f01.y * w1;
                op[im*2+1] += f23.x * w0 + f23.y * w1;
            }
#pragma unroll
            for (int i = 0; i < 4; ++i) {
                op[i] += __shfl_xor_sync(0xffffffffu, op[i], 1);
                op[i] += __shfl_xor_sync(0xffffffffu, op[i], 2);
            }
            if (t == 0) {
#pragma unroll
                for (int im = 0; im < 2; ++im)
#pragma unroll
                for (int rh = 0; rh < 2; ++rh)
                    zh[ng * 64 + warpM + 16 * im + 8 * rh + g] = op[im*2+rh];
            }
        }
        hbar(barid);                      // OP visible (d reads done)

        if (htid < 64) {
            const float v = zh[htid] + zh[64 + htid]
                          + zh[128 + htid] + zh[192 + htid] + cf[CF_BO];
            float e;  asm("ex2.approx.f32 %0, %1;" : "=f"(e)  : "f"(-1.442695041f * v));
            float sg; asm("rcp.approx.f32 %0, %1;" : "=f"(sg) : "f"(1.0f + e));
            if (nb + htid < Nn) out[nb + htid] = sg;
        }
    }
}

// ---------------- launch ----------------
extern "C" void kernel_launch(void* const* d_in, const int* in_sizes, int n_in,
                              void* d_out, int out_size)
{
    // order: x, edge_index, edge_attr, W1, b1, We1, be1, We2, be2,
    //        Wd1, bd1, Wd2, bd2, Wo, bo
    const float* edge_attr = (const float*)d_in[2];
    const float* W1  = (const float*)d_in[3];
    const float* b1  = (const float*)d_in[4];
    const float* We1 = (const float*)d_in[5];
    const float* be1 = (const float*)d_in[6];
    const float* We2 = (const float*)d_in[7];
    const float* be2 = (const float*)d_in[8];
    const float* Wd1 = (const float*)d_in[9];
    const float* bd1 = (const float*)d_in[10];
    const float* Wd2 = (const float*)d_in[11];
    const float* bd2 = (const float*)d_in[12];
    const float* Wo  = (const float*)d_in[13];
    const float* bo  = (const float*)d_in[14];
    float* out = (float*)d_out;

    const int Nn = out_size;
    const int ntiles = (Nn + 127) / 128;

    prep_weights<<<304, 256>>>(W1, We1, Wd2, Wd1);

    cudaFuncSetAttribute(gnn_mma_kernel,
                         cudaFuncAttributeMaxDynamicSharedMemorySize, SMEM_BYTES);
    int sms = 148;
    cudaDeviceGetAttribute(&sms, cudaDevAttrMultiProcessorCount, 0);
    const int grid = ntiles < sms ? ntiles : sms;

    gnn_mma_kernel<<<grid, 512, SMEM_BYTES>>>(
        edge_attr, b1, be1, We2, be2, bd1, bd2, Wo, bo, out, Nn, ntiles);
}